// round 7
// baseline (speedup 1.0000x reference)
#include <cuda_runtime.h>
#include <float.h>

#define NNODES 100000
#define F_IN   128
#define D1     256      // 8 heads * 32
#define HEADS  8
#define NCLS   40
#define NEG    0.2f
#define EMAX   1600000
#define SCAN_B 1024

// ---------------- scratch (device globals; no allocation allowed) ----------
__device__ __align__(16) float g_h1[NNODES * D1];      // x @ W1
__device__ __align__(16) float g_h2[NNODES * D1];      // layer-1 output
__device__ float g_ssrc1[NNODES * HEADS];
__device__ float g_sdst1[NNODES * HEADS];
__device__ float g_pself1[NNODES * HEADS];
__device__ __align__(16) float g_h3[NNODES * NCLS];    // h2 @ W2
__device__ float g_ssrc2[NNODES];
__device__ float g_sdst2[NNODES];
__device__ float g_pself2[NNODES];
// CSR (dst-binned edges)
__device__ int g_counts[NNODES];
__device__ int g_rowptr[NNODES + 1];
__device__ int g_cursor[NNODES];
__device__ int g_csr_src[EMAX];
__device__ int g_bsum[(NNODES + SCAN_B - 1) / SCAN_B];
__device__ int g_boff[(NNODES + SCAN_B - 1) / SCAN_B];

__device__ __forceinline__ float lrelu(float v) { return v >= 0.f ? v : NEG * v; }

// ======================= CSR build ==========================================
__global__ __launch_bounds__(256) void zero_counts_kernel(int n) {
    int i = blockIdx.x * blockDim.x + threadIdx.x;
    if (i < n) g_counts[i] = 0;
}

__global__ __launch_bounds__(256) void hist_kernel(const int* __restrict__ dst, int E) {
    int e = blockIdx.x * blockDim.x + threadIdx.x;
    if (e < E) atomicAdd(&g_counts[dst[e]], 1);
}

__global__ __launch_bounds__(SCAN_B) void scan_sums_kernel(int n) {
    __shared__ int ws[32];
    int i = blockIdx.x * SCAN_B + threadIdx.x;
    int v = (i < n) ? g_counts[i] : 0;
    int lane = threadIdx.x & 31, w = threadIdx.x >> 5;
    int s = v;
#pragma unroll
    for (int o = 16; o; o >>= 1) s += __shfl_xor_sync(0xffffffffu, s, o);
    if (lane == 0) ws[w] = s;
    __syncthreads();
    if (w == 0) {
        int t = ws[lane];
#pragma unroll
        for (int o = 16; o; o >>= 1) t += __shfl_xor_sync(0xffffffffu, t, o);
        if (lane == 0) g_bsum[blockIdx.x] = t;
    }
}

__global__ __launch_bounds__(SCAN_B) void scan_offsets_kernel(int nb, int n) {
    __shared__ int ws[32];
    int lane = threadIdx.x & 31, w = threadIdx.x >> 5;
    int v = (threadIdx.x < nb) ? g_bsum[threadIdx.x] : 0;
    int x = v;
#pragma unroll
    for (int o = 1; o < 32; o <<= 1) {
        int y = __shfl_up_sync(0xffffffffu, x, o);
        if (lane >= o) x += y;
    }
    if (lane == 31) ws[w] = x;
    __syncthreads();
    if (w == 0) {
        int s = ws[lane];
#pragma unroll
        for (int o = 1; o < 32; o <<= 1) {
            int y = __shfl_up_sync(0xffffffffu, s, o);
            if (lane >= o) s += y;
        }
        ws[lane] = s;
    }
    __syncthreads();
    int incl = x + (w > 0 ? ws[w - 1] : 0);
    if (threadIdx.x < nb) g_boff[threadIdx.x] = incl - v;
    if (threadIdx.x == nb - 1) g_rowptr[n] = incl;
}

__global__ __launch_bounds__(SCAN_B) void scan_apply_kernel(int n) {
    __shared__ int ws[32];
    int i = blockIdx.x * SCAN_B + threadIdx.x;
    int v = (i < n) ? g_counts[i] : 0;
    int lane = threadIdx.x & 31, w = threadIdx.x >> 5;
    int x = v;
#pragma unroll
    for (int o = 1; o < 32; o <<= 1) {
        int y = __shfl_up_sync(0xffffffffu, x, o);
        if (lane >= o) x += y;
    }
    if (lane == 31) ws[w] = x;
    __syncthreads();
    if (w == 0) {
        int s = ws[lane];
#pragma unroll
        for (int o = 1; o < 32; o <<= 1) {
            int y = __shfl_up_sync(0xffffffffu, s, o);
            if (lane >= o) s += y;
        }
        ws[lane] = s;
    }
    __syncthreads();
    int excl = x - v + (w > 0 ? ws[w - 1] : 0) + g_boff[blockIdx.x];
    if (i < n) { g_rowptr[i] = excl; g_cursor[i] = excl; }
}

__global__ __launch_bounds__(256) void scatter_kernel(const int* __restrict__ src,
                                                      const int* __restrict__ dst, int E) {
    int e = blockIdx.x * blockDim.x + threadIdx.x;
    if (e >= E) return;
    int pos = atomicAdd(&g_cursor[dst[e]], 1);
    g_csr_src[pos] = src[e];
}

// ======== GEMM1 + fused scores: h1 = x@W1; also s_src/s_dst/p_self ==========
#define TM 64
#define TN 64
#define TK 16
#define APAD 4

__global__ __launch_bounds__(256) void gemm1_kernel(const float* __restrict__ A,
                                                    const float* __restrict__ B,
                                                    const float* __restrict__ asrc,
                                                    const float* __restrict__ adst,
                                                    int M) {
    __shared__ float As[TK][TM + APAD];
    __shared__ float Bs[TK][TN + APAD];
    __shared__ float sS[TM][2];
    __shared__ float sD[TM][2];
    int tid = threadIdx.x;
    int tx = tid & 15, ty = tid >> 4;
    int rowBase = blockIdx.y * TM;
    int colBase = blockIdx.x * TN;
    float acc[4][4] = {};

    if (tid < TM) { sS[tid][0] = 0.f; sS[tid][1] = 0.f; sD[tid][0] = 0.f; sD[tid][1] = 0.f; }

    for (int k0 = 0; k0 < F_IN; k0 += TK) {
        {
            int r  = tid >> 2;
            int kg = (tid & 3) * 4;
            float4 v = make_float4(0.f, 0.f, 0.f, 0.f);
            int gr = rowBase + r;
            if (gr < M) v = *(const float4*)&A[(size_t)gr * F_IN + k0 + kg];
            As[kg + 0][r] = v.x; As[kg + 1][r] = v.y;
            As[kg + 2][r] = v.z; As[kg + 3][r] = v.w;
        }
        {
            int kk = tid >> 4;
            int c  = (tid & 15) * 4;
            float4 v = *(const float4*)&B[(size_t)(k0 + kk) * D1 + colBase + c];
            Bs[kk][c + 0] = v.x; Bs[kk][c + 1] = v.y;
            Bs[kk][c + 2] = v.z; Bs[kk][c + 3] = v.w;
        }
        __syncthreads();
#pragma unroll
        for (int kk = 0; kk < TK; kk++) {
            float a0 = As[kk][ty * 4 + 0], a1 = As[kk][ty * 4 + 1];
            float a2 = As[kk][ty * 4 + 2], a3 = As[kk][ty * 4 + 3];
            float b0 = Bs[kk][tx * 4 + 0], b1 = Bs[kk][tx * 4 + 1];
            float b2 = Bs[kk][tx * 4 + 2], b3 = Bs[kk][tx * 4 + 3];
            acc[0][0] += a0 * b0; acc[0][1] += a0 * b1; acc[0][2] += a0 * b2; acc[0][3] += a0 * b3;
            acc[1][0] += a1 * b0; acc[1][1] += a1 * b1; acc[1][2] += a1 * b2; acc[1][3] += a1 * b3;
            acc[2][0] += a2 * b0; acc[2][1] += a2 * b1; acc[2][2] += a2 * b2; acc[2][3] += a2 * b3;
            acc[3][0] += a3 * b0; acc[3][1] += a3 * b1; acc[3][2] += a3 * b2; acc[3][3] += a3 * b3;
        }
        __syncthreads();
    }
#pragma unroll
    for (int i = 0; i < 4; i++) {
        int gr = rowBase + ty * 4 + i;
        if (gr < M) {
            float4 o = make_float4(acc[i][0], acc[i][1], acc[i][2], acc[i][3]);
            *(float4*)&g_h1[(size_t)gr * D1 + colBase + tx * 4] = o;
        }
    }
    float4 av = *(const float4*)&asrc[colBase + tx * 4];
    float4 dv = *(const float4*)&adst[colBase + tx * 4];
    int hh = tx >> 3;
#pragma unroll
    for (int i = 0; i < 4; i++) {
        float ps = acc[i][0]*av.x + acc[i][1]*av.y + acc[i][2]*av.z + acc[i][3]*av.w;
        float pd = acc[i][0]*dv.x + acc[i][1]*dv.y + acc[i][2]*dv.z + acc[i][3]*dv.w;
        atomicAdd(&sS[ty * 4 + i][hh], ps);
        atomicAdd(&sD[ty * 4 + i][hh], pd);
    }
    __syncthreads();
    if (tid < 2 * TM) {
        int row = tid >> 1, h2i = tid & 1;
        int gr = rowBase + row;
        if (gr < M) {
            int head = blockIdx.x * 2 + h2i;
            float ps = sS[row][h2i], pd = sD[row][h2i];
            g_ssrc1[gr * HEADS + head] = ps;
            g_sdst1[gr * HEADS + head] = pd;
            g_pself1[gr * HEADS + head] = __expf(lrelu(ps + pd));
        }
    }
}

// ======== aggregate1: 4 warps/node (64 ch each), CSR, unroll-2 ==============
__global__ __launch_bounds__(256) void aggregate1_kernel(const float* __restrict__ b1, int M) {
    int gw   = (blockIdx.x * blockDim.x + threadIdx.x) >> 5;
    int node = gw >> 2;
    int quarter = gw & 3;
    int lane = threadIdx.x & 31;
    if (node >= M) return;
    int ch = quarter * 64 + lane * 2;        // 2 channels per lane
    int h  = ch >> 5;
    float sdst_h = g_sdst1[node * HEADS + h];
    float pself  = g_pself1[node * HEADS + h];
    size_t nb = (size_t)node * D1 + ch;
    float2 a = *(const float2*)&g_h1[nb];
    float c0 = a.x * pself, c1 = a.y * pself;
    float denom = pself;
    int beg = g_rowptr[node], end = g_rowptr[node + 1];
    int i = beg;
    for (; i + 2 <= end; i += 2) {
        int s0 = __ldg(&g_csr_src[i]);
        int s1 = __ldg(&g_csr_src[i + 1]);
        float p0 = __expf(lrelu(__ldg(&g_ssrc1[s0 * HEADS + h]) + sdst_h));
        float p1 = __expf(lrelu(__ldg(&g_ssrc1[s1 * HEADS + h]) + sdst_h));
        float2 v0 = *(const float2*)&g_h1[(size_t)s0 * D1 + ch];
        float2 v1 = *(const float2*)&g_h1[(size_t)s1 * D1 + ch];
        c0 += v0.x * p0 + v1.x * p1;
        c1 += v0.y * p0 + v1.y * p1;
        denom += p0 + p1;
    }
    if (i < end) {
        int s = __ldg(&g_csr_src[i]);
        float p = __expf(lrelu(__ldg(&g_ssrc1[s * HEADS + h]) + sdst_h));
        float2 v = *(const float2*)&g_h1[(size_t)s * D1 + ch];
        c0 += v.x * p; c1 += v.y * p;
        denom += p;
    }
    float inv = __frcp_rn(denom);
    float2 bb = *(const float2*)&b1[ch];
    float2 o;
    o.x = fmaxf(c0 * inv + bb.x, 0.f);
    o.y = fmaxf(c1 * inv + bb.y, 0.f);
    *(float2*)&g_h2[nb] = o;
}

// ======== GEMM2 + fused scores2: h3 = h2@W2; s_src2/s_dst2/p_self2 =========
__global__ __launch_bounds__(256) void gemm2_kernel(const float* __restrict__ B,
                                                    const float* __restrict__ asrc,
                                                    const float* __restrict__ adst,
                                                    int M) {
    __shared__ float Bs[D1 * NCLS];  // 40 KB
    for (int i = threadIdx.x; i < D1 * NCLS; i += 256) Bs[i] = B[i];
    __syncthreads();
    int warp = threadIdx.x >> 5, lane = threadIdx.x & 31;
    float as0 = asrc[lane], ad0 = adst[lane];
    float as1 = (lane < 8) ? asrc[32 + lane] : 0.f;
    float ad1 = (lane < 8) ? adst[32 + lane] : 0.f;
    const int RPW = 16;
    int rowBase = (blockIdx.x * 8 + warp) * RPW;
    for (int i = 0; i < RPW; i++) {
        int row = rowBase + i;
        if (row >= M) return;
        const float* a = &g_h2[(size_t)row * D1];
        float acc0 = 0.f, acc1 = 0.f;
#pragma unroll 4
        for (int k = 0; k < D1; k += 4) {
            float4 av = *(const float4*)(a + k);   // broadcast load
            acc0 += av.x * Bs[(k + 0) * NCLS + lane];
            acc0 += av.y * Bs[(k + 1) * NCLS + lane];
            acc0 += av.z * Bs[(k + 2) * NCLS + lane];
            acc0 += av.w * Bs[(k + 3) * NCLS + lane];
            if (lane < 8) {
                acc1 += av.x * Bs[(k + 0) * NCLS + 32 + lane];
                acc1 += av.y * Bs[(k + 1) * NCLS + 32 + lane];
                acc1 += av.z * Bs[(k + 2) * NCLS + 32 + lane];
                acc1 += av.w * Bs[(k + 3) * NCLS + 32 + lane];
            }
        }
        g_h3[(size_t)row * NCLS + lane] = acc0;
        if (lane < 8) g_h3[(size_t)row * NCLS + 32 + lane] = acc1;
        float ps = acc0 * as0 + ((lane < 8) ? acc1 * as1 : 0.f);
        float pd = acc0 * ad0 + ((lane < 8) ? acc1 * ad1 : 0.f);
#pragma unroll
        for (int o = 16; o; o >>= 1) {
            ps += __shfl_xor_sync(0xffffffffu, ps, o);
            pd += __shfl_xor_sync(0xffffffffu, pd, o);
        }
        if (lane == 0) {
            g_ssrc2[row] = ps;
            g_sdst2[row] = pd;
            g_pself2[row] = __expf(lrelu(ps + pd));
        }
    }
}

// ======== aggregate2: node-per-warp, CSR, unroll-2, fused log_softmax ======
__global__ __launch_bounds__(256) void aggregate2_kernel(const float* __restrict__ b2,
                                                         float* __restrict__ out, int M) {
    int wid  = (blockIdx.x * blockDim.x + threadIdx.x) >> 5;
    int lane = threadIdx.x & 31;
    if (wid >= M) return;
    float sdst = g_sdst2[wid];
    float pself = g_pself2[wid];
    size_t nb = (size_t)wid * NCLS;
    float v0 = g_h3[nb + lane] * pself;
    float v1 = (lane < 8) ? g_h3[nb + 32 + lane] * pself : 0.f;
    float denom = pself;
    int beg = g_rowptr[wid], end = g_rowptr[wid + 1];
    int i = beg;
    for (; i + 2 <= end; i += 2) {
        int s0 = __ldg(&g_csr_src[i]);
        int s1 = __ldg(&g_csr_src[i + 1]);
        float p0 = __expf(lrelu(__ldg(&g_ssrc2[s0]) + sdst));
        float p1 = __expf(lrelu(__ldg(&g_ssrc2[s1]) + sdst));
        size_t sb0 = (size_t)s0 * NCLS, sb1 = (size_t)s1 * NCLS;
        v0 += p0 * g_h3[sb0 + lane] + p1 * g_h3[sb1 + lane];
        if (lane < 8) v1 += p0 * g_h3[sb0 + 32 + lane] + p1 * g_h3[sb1 + 32 + lane];
        denom += p0 + p1;
    }
    if (i < end) {
        int s = __ldg(&g_csr_src[i]);
        float p = __expf(lrelu(__ldg(&g_ssrc2[s]) + sdst));
        size_t sb = (size_t)s * NCLS;
        v0 += p * g_h3[sb + lane];
        if (lane < 8) v1 += p * g_h3[sb + 32 + lane];
        denom += p;
    }
    float inv = __frcp_rn(denom);
    float z0 = v0 * inv + b2[lane];
    float z1 = (lane < 8) ? (v1 * inv + b2[32 + lane]) : -FLT_MAX;
    float m = fmaxf(z0, z1);
#pragma unroll
    for (int o = 16; o; o >>= 1) m = fmaxf(m, __shfl_xor_sync(0xffffffffu, m, o));
    float s = expf(z0 - m) + ((lane < 8) ? expf(z1 - m) : 0.f);
#pragma unroll
    for (int o = 16; o; o >>= 1) s += __shfl_xor_sync(0xffffffffu, s, o);
    float ls = logf(s);
    out[nb + lane] = z0 - m - ls;
    if (lane < 8) out[nb + 32 + lane] = z1 - m - ls;
}

// ---------------------------------------------------------------------------
extern "C" void kernel_launch(void* const* d_in, const int* in_sizes, int n_in,
                              void* d_out, int out_size) {
    const float* x     = (const float*)d_in[0];
    const int*   ei    = (const int*)d_in[1];      // JAX x64 disabled -> int32
    const float* W1    = (const float*)d_in[2];
    const float* asrc1 = (const float*)d_in[3];
    const float* adst1 = (const float*)d_in[4];
    const float* b1    = (const float*)d_in[5];
    const float* W2    = (const float*)d_in[6];
    const float* asrc2 = (const float*)d_in[7];
    const float* adst2 = (const float*)d_in[8];
    const float* b2    = (const float*)d_in[9];
    float* out = (float*)d_out;

    int M = in_sizes[0] / F_IN;        // 100000
    int E = in_sizes[1] / 2;           // 1600000
    const int* src = ei;
    const int* dst = ei + E;
    int NB = (M + SCAN_B - 1) / SCAN_B;

    // CSR build
    zero_counts_kernel<<<(M + 255) / 256, 256>>>(M);
    hist_kernel<<<(E + 255) / 256, 256>>>(dst, E);
    scan_sums_kernel<<<NB, SCAN_B>>>(M);
    scan_offsets_kernel<<<1, SCAN_B>>>(NB, M);
    scan_apply_kernel<<<NB, SCAN_B>>>(M);
    scatter_kernel<<<(E + 255) / 256, 256>>>(src, dst, E);

    // Layer 1
    {
        dim3 grid(D1 / TN, (M + TM - 1) / TM);
        gemm1_kernel<<<grid, 256>>>(x, W1, asrc1, adst1, M);
    }
    aggregate1_kernel<<<(M * 128 + 255) / 256, 256>>>(b1, M);

    // Layer 2
    gemm2_kernel<<<(M + 127) / 128, 256>>>(W2, asrc2, adst2, M);
    aggregate2_kernel<<<(M * 32 + 255) / 256, 256>>>(b2, out, M);
}

// round 8
// speedup vs baseline: 1.1238x; 1.1238x over previous
#include <cuda_runtime.h>
#include <float.h>

#define NNODES 100000
#define F_IN   128
#define D1     256      // 8 heads * 32
#define HEADS  8
#define NCLS   40
#define NEG    0.2f
#define EMAX   1600000
#define SCAN_B 1024

// ---------------- scratch (device globals; no allocation allowed) ----------
__device__ __align__(16) float g_h1[NNODES * D1];      // x @ W1
__device__ __align__(16) float g_h2[NNODES * D1];      // layer-1 output
__device__ float g_ssrc1[NNODES * HEADS];
__device__ float g_sdst1[NNODES * HEADS];
__device__ float g_pself1[NNODES * HEADS];
__device__ __align__(16) float g_h3[NNODES * NCLS];    // h2 @ W2
__device__ float g_ssrc2[NNODES];
__device__ float g_sdst2[NNODES];
__device__ float g_pself2[NNODES];
// CSR (dst-binned edges)
__device__ int g_counts[NNODES];
__device__ int g_rowptr[NNODES + 1];
__device__ int g_cursor[NNODES];
__device__ int g_csr_src[EMAX];
__device__ int g_bsum[(NNODES + SCAN_B - 1) / SCAN_B];
__device__ int g_boff[(NNODES + SCAN_B - 1) / SCAN_B];

__device__ __forceinline__ float lrelu(float v) { return v >= 0.f ? v : NEG * v; }

// ======================= CSR build ==========================================
__global__ __launch_bounds__(256) void zero_counts_kernel(int n) {
    int i = blockIdx.x * blockDim.x + threadIdx.x;
    if (i < n) g_counts[i] = 0;
}

__global__ __launch_bounds__(256) void hist_kernel(const int* __restrict__ dst, int E) {
    int e = blockIdx.x * blockDim.x + threadIdx.x;
    if (e < E) atomicAdd(&g_counts[dst[e]], 1);
}

__global__ __launch_bounds__(SCAN_B) void scan_sums_kernel(int n) {
    __shared__ int ws[32];
    int i = blockIdx.x * SCAN_B + threadIdx.x;
    int v = (i < n) ? g_counts[i] : 0;
    int lane = threadIdx.x & 31, w = threadIdx.x >> 5;
    int s = v;
#pragma unroll
    for (int o = 16; o; o >>= 1) s += __shfl_xor_sync(0xffffffffu, s, o);
    if (lane == 0) ws[w] = s;
    __syncthreads();
    if (w == 0) {
        int t = ws[lane];
#pragma unroll
        for (int o = 16; o; o >>= 1) t += __shfl_xor_sync(0xffffffffu, t, o);
        if (lane == 0) g_bsum[blockIdx.x] = t;
    }
}

__global__ __launch_bounds__(SCAN_B) void scan_offsets_kernel(int nb, int n) {
    __shared__ int ws[32];
    int lane = threadIdx.x & 31, w = threadIdx.x >> 5;
    int v = (threadIdx.x < nb) ? g_bsum[threadIdx.x] : 0;
    int x = v;
#pragma unroll
    for (int o = 1; o < 32; o <<= 1) {
        int y = __shfl_up_sync(0xffffffffu, x, o);
        if (lane >= o) x += y;
    }
    if (lane == 31) ws[w] = x;
    __syncthreads();
    if (w == 0) {
        int s = ws[lane];
#pragma unroll
        for (int o = 1; o < 32; o <<= 1) {
            int y = __shfl_up_sync(0xffffffffu, s, o);
            if (lane >= o) s += y;
        }
        ws[lane] = s;
    }
    __syncthreads();
    int incl = x + (w > 0 ? ws[w - 1] : 0);
    if (threadIdx.x < nb) g_boff[threadIdx.x] = incl - v;
    if (threadIdx.x == nb - 1) g_rowptr[n] = incl;
}

__global__ __launch_bounds__(SCAN_B) void scan_apply_kernel(int n) {
    __shared__ int ws[32];
    int i = blockIdx.x * SCAN_B + threadIdx.x;
    int v = (i < n) ? g_counts[i] : 0;
    int lane = threadIdx.x & 31, w = threadIdx.x >> 5;
    int x = v;
#pragma unroll
    for (int o = 1; o < 32; o <<= 1) {
        int y = __shfl_up_sync(0xffffffffu, x, o);
        if (lane >= o) x += y;
    }
    if (lane == 31) ws[w] = x;
    __syncthreads();
    if (w == 0) {
        int s = ws[lane];
#pragma unroll
        for (int o = 1; o < 32; o <<= 1) {
            int y = __shfl_up_sync(0xffffffffu, s, o);
            if (lane >= o) s += y;
        }
        ws[lane] = s;
    }
    __syncthreads();
    int excl = x - v + (w > 0 ? ws[w - 1] : 0) + g_boff[blockIdx.x];
    if (i < n) { g_rowptr[i] = excl; g_cursor[i] = excl; }
}

__global__ __launch_bounds__(256) void scatter_kernel(const int* __restrict__ src,
                                                      const int* __restrict__ dst, int E) {
    int e = blockIdx.x * blockDim.x + threadIdx.x;
    if (e >= E) return;
    int pos = atomicAdd(&g_cursor[dst[e]], 1);
    g_csr_src[pos] = src[e];
}

// ======== GEMM1 + fused scores: h1 = x@W1; also s_src/s_dst/p_self ==========
#define TM 64
#define TN 64
#define TK 16
#define APAD 4

__global__ __launch_bounds__(256) void gemm1_kernel(const float* __restrict__ A,
                                                    const float* __restrict__ B,
                                                    const float* __restrict__ asrc,
                                                    const float* __restrict__ adst,
                                                    int M) {
    __shared__ float As[TK][TM + APAD];
    __shared__ float Bs[TK][TN + APAD];
    __shared__ float sS[TM][2];
    __shared__ float sD[TM][2];
    int tid = threadIdx.x;
    int tx = tid & 15, ty = tid >> 4;
    int rowBase = blockIdx.y * TM;
    int colBase = blockIdx.x * TN;
    float acc[4][4] = {};

    if (tid < TM) { sS[tid][0] = 0.f; sS[tid][1] = 0.f; sD[tid][0] = 0.f; sD[tid][1] = 0.f; }

    for (int k0 = 0; k0 < F_IN; k0 += TK) {
        {
            int r  = tid >> 2;
            int kg = (tid & 3) * 4;
            float4 v = make_float4(0.f, 0.f, 0.f, 0.f);
            int gr = rowBase + r;
            if (gr < M) v = *(const float4*)&A[(size_t)gr * F_IN + k0 + kg];
            As[kg + 0][r] = v.x; As[kg + 1][r] = v.y;
            As[kg + 2][r] = v.z; As[kg + 3][r] = v.w;
        }
        {
            int kk = tid >> 4;
            int c  = (tid & 15) * 4;
            float4 v = *(const float4*)&B[(size_t)(k0 + kk) * D1 + colBase + c];
            Bs[kk][c + 0] = v.x; Bs[kk][c + 1] = v.y;
            Bs[kk][c + 2] = v.z; Bs[kk][c + 3] = v.w;
        }
        __syncthreads();
#pragma unroll
        for (int kk = 0; kk < TK; kk++) {
            float a0 = As[kk][ty * 4 + 0], a1 = As[kk][ty * 4 + 1];
            float a2 = As[kk][ty * 4 + 2], a3 = As[kk][ty * 4 + 3];
            float b0 = Bs[kk][tx * 4 + 0], b1 = Bs[kk][tx * 4 + 1];
            float b2 = Bs[kk][tx * 4 + 2], b3 = Bs[kk][tx * 4 + 3];
            acc[0][0] += a0 * b0; acc[0][1] += a0 * b1; acc[0][2] += a0 * b2; acc[0][3] += a0 * b3;
            acc[1][0] += a1 * b0; acc[1][1] += a1 * b1; acc[1][2] += a1 * b2; acc[1][3] += a1 * b3;
            acc[2][0] += a2 * b0; acc[2][1] += a2 * b1; acc[2][2] += a2 * b2; acc[2][3] += a2 * b3;
            acc[3][0] += a3 * b0; acc[3][1] += a3 * b1; acc[3][2] += a3 * b2; acc[3][3] += a3 * b3;
        }
        __syncthreads();
    }
#pragma unroll
    for (int i = 0; i < 4; i++) {
        int gr = rowBase + ty * 4 + i;
        if (gr < M) {
            float4 o = make_float4(acc[i][0], acc[i][1], acc[i][2], acc[i][3]);
            *(float4*)&g_h1[(size_t)gr * D1 + colBase + tx * 4] = o;
        }
    }
    float4 av = *(const float4*)&asrc[colBase + tx * 4];
    float4 dv = *(const float4*)&adst[colBase + tx * 4];
    int hh = tx >> 3;
#pragma unroll
    for (int i = 0; i < 4; i++) {
        float ps = acc[i][0]*av.x + acc[i][1]*av.y + acc[i][2]*av.z + acc[i][3]*av.w;
        float pd = acc[i][0]*dv.x + acc[i][1]*dv.y + acc[i][2]*dv.z + acc[i][3]*dv.w;
        atomicAdd(&sS[ty * 4 + i][hh], ps);
        atomicAdd(&sD[ty * 4 + i][hh], pd);
    }
    __syncthreads();
    if (tid < 2 * TM) {
        int row = tid >> 1, h2i = tid & 1;
        int gr = rowBase + row;
        if (gr < M) {
            int head = blockIdx.x * 2 + h2i;
            float ps = sS[row][h2i], pd = sD[row][h2i];
            g_ssrc1[gr * HEADS + head] = ps;
            g_sdst1[gr * HEADS + head] = pd;
            g_pself1[gr * HEADS + head] = __expf(lrelu(ps + pd));
        }
    }
}

// ======== aggregate1: 2 warps/node (128 ch each), CSR, unroll-2 =============
__global__ __launch_bounds__(256) void aggregate1_kernel(const float* __restrict__ b1, int M) {
    int gw   = (blockIdx.x * blockDim.x + threadIdx.x) >> 5;
    int node = gw >> 1;
    int half = gw & 1;
    int lane = threadIdx.x & 31;
    if (node >= M) return;
    int ch = half * 128 + lane * 4;          // 4 channels per lane
    int h  = ch >> 5;
    float sdst_h = g_sdst1[node * HEADS + h];
    float pself  = g_pself1[node * HEADS + h];
    size_t nb = (size_t)node * D1 + ch;
    float4 a = *(const float4*)&g_h1[nb];
    float c0 = a.x * pself, c1 = a.y * pself, c2 = a.z * pself, c3 = a.w * pself;
    float denom = pself;
    int beg = g_rowptr[node], end = g_rowptr[node + 1];
    int i = beg;
    for (; i + 2 <= end; i += 2) {
        int s0 = __ldg(&g_csr_src[i]);
        int s1 = __ldg(&g_csr_src[i + 1]);
        float p0 = __expf(lrelu(__ldg(&g_ssrc1[s0 * HEADS + h]) + sdst_h));
        float p1 = __expf(lrelu(__ldg(&g_ssrc1[s1 * HEADS + h]) + sdst_h));
        float4 v0 = *(const float4*)&g_h1[(size_t)s0 * D1 + ch];
        float4 v1 = *(const float4*)&g_h1[(size_t)s1 * D1 + ch];
        c0 += v0.x * p0 + v1.x * p1;
        c1 += v0.y * p0 + v1.y * p1;
        c2 += v0.z * p0 + v1.z * p1;
        c3 += v0.w * p0 + v1.w * p1;
        denom += p0 + p1;
    }
    if (i < end) {
        int s = __ldg(&g_csr_src[i]);
        float p = __expf(lrelu(__ldg(&g_ssrc1[s * HEADS + h]) + sdst_h));
        float4 v = *(const float4*)&g_h1[(size_t)s * D1 + ch];
        c0 += v.x * p; c1 += v.y * p; c2 += v.z * p; c3 += v.w * p;
        denom += p;
    }
    float inv = __frcp_rn(denom);
    float4 bb = *(const float4*)&b1[ch];
    float4 o;
    o.x = fmaxf(c0 * inv + bb.x, 0.f);
    o.y = fmaxf(c1 * inv + bb.y, 0.f);
    o.z = fmaxf(c2 * inv + bb.z, 0.f);
    o.w = fmaxf(c3 * inv + bb.w, 0.f);
    *(float4*)&g_h2[nb] = o;
}

// ======== GEMM2 + fused scores2: h3 = h2@W2; s_src2/s_dst2/p_self2 =========
__global__ __launch_bounds__(256) void gemm2_kernel(const float* __restrict__ B,
                                                    const float* __restrict__ asrc,
                                                    const float* __restrict__ adst,
                                                    int M) {
    __shared__ float Bs[D1 * NCLS];  // 40 KB
    for (int i = threadIdx.x; i < D1 * NCLS; i += 256) Bs[i] = B[i];
    __syncthreads();
    int warp = threadIdx.x >> 5, lane = threadIdx.x & 31;
    float as0 = asrc[lane], ad0 = adst[lane];
    float as1 = (lane < 8) ? asrc[32 + lane] : 0.f;
    float ad1 = (lane < 8) ? adst[32 + lane] : 0.f;
    const int RPW = 16;
    int rowBase = (blockIdx.x * 8 + warp) * RPW;
    for (int i = 0; i < RPW; i++) {
        int row = rowBase + i;
        if (row >= M) return;
        const float* a = &g_h2[(size_t)row * D1];
        float acc0 = 0.f, acc1 = 0.f;
#pragma unroll 4
        for (int k = 0; k < D1; k += 4) {
            float4 av = *(const float4*)(a + k);   // broadcast load
            acc0 += av.x * Bs[(k + 0) * NCLS + lane];
            acc0 += av.y * Bs[(k + 1) * NCLS + lane];
            acc0 += av.z * Bs[(k + 2) * NCLS + lane];
            acc0 += av.w * Bs[(k + 3) * NCLS + lane];
            if (lane < 8) {
                acc1 += av.x * Bs[(k + 0) * NCLS + 32 + lane];
                acc1 += av.y * Bs[(k + 1) * NCLS + 32 + lane];
                acc1 += av.z * Bs[(k + 2) * NCLS + 32 + lane];
                acc1 += av.w * Bs[(k + 3) * NCLS + 32 + lane];
            }
        }
        g_h3[(size_t)row * NCLS + lane] = acc0;
        if (lane < 8) g_h3[(size_t)row * NCLS + 32 + lane] = acc1;
        float ps = acc0 * as0 + ((lane < 8) ? acc1 * as1 : 0.f);
        float pd = acc0 * ad0 + ((lane < 8) ? acc1 * ad1 : 0.f);
#pragma unroll
        for (int o = 16; o; o >>= 1) {
            ps += __shfl_xor_sync(0xffffffffu, ps, o);
            pd += __shfl_xor_sync(0xffffffffu, pd, o);
        }
        if (lane == 0) {
            g_ssrc2[row] = ps;
            g_sdst2[row] = pd;
            g_pself2[row] = __expf(lrelu(ps + pd));
        }
    }
}

// ======== aggregate2: node-per-warp, CSR, unroll-2, fused log_softmax ======
__global__ __launch_bounds__(256) void aggregate2_kernel(const float* __restrict__ b2,
                                                         float* __restrict__ out, int M) {
    int wid  = (blockIdx.x * blockDim.x + threadIdx.x) >> 5;
    int lane = threadIdx.x & 31;
    if (wid >= M) return;
    float sdst = g_sdst2[wid];
    float pself = g_pself2[wid];
    size_t nb = (size_t)wid * NCLS;
    float v0 = g_h3[nb + lane] * pself;
    float v1 = (lane < 8) ? g_h3[nb + 32 + lane] * pself : 0.f;
    float denom = pself;
    int beg = g_rowptr[wid], end = g_rowptr[wid + 1];
    int i = beg;
    for (; i + 2 <= end; i += 2) {
        int s0 = __ldg(&g_csr_src[i]);
        int s1 = __ldg(&g_csr_src[i + 1]);
        float p0 = __expf(lrelu(__ldg(&g_ssrc2[s0]) + sdst));
        float p1 = __expf(lrelu(__ldg(&g_ssrc2[s1]) + sdst));
        size_t sb0 = (size_t)s0 * NCLS, sb1 = (size_t)s1 * NCLS;
        v0 += p0 * g_h3[sb0 + lane] + p1 * g_h3[sb1 + lane];
        if (lane < 8) v1 += p0 * g_h3[sb0 + 32 + lane] + p1 * g_h3[sb1 + 32 + lane];
        denom += p0 + p1;
    }
    if (i < end) {
        int s = __ldg(&g_csr_src[i]);
        float p = __expf(lrelu(__ldg(&g_ssrc2[s]) + sdst));
        size_t sb = (size_t)s * NCLS;
        v0 += p * g_h3[sb + lane];
        if (lane < 8) v1 += p * g_h3[sb + 32 + lane];
        denom += p;
    }
    float inv = __frcp_rn(denom);
    float z0 = v0 * inv + b2[lane];
    float z1 = (lane < 8) ? (v1 * inv + b2[32 + lane]) : -FLT_MAX;
    float m = fmaxf(z0, z1);
#pragma unroll
    for (int o = 16; o; o >>= 1) m = fmaxf(m, __shfl_xor_sync(0xffffffffu, m, o));
    float s = expf(z0 - m) + ((lane < 8) ? expf(z1 - m) : 0.f);
#pragma unroll
    for (int o = 16; o; o >>= 1) s += __shfl_xor_sync(0xffffffffu, s, o);
    float ls = logf(s);
    out[nb + lane] = z0 - m - ls;
    if (lane < 8) out[nb + 32 + lane] = z1 - m - ls;
}

// ---------------------------------------------------------------------------
extern "C" void kernel_launch(void* const* d_in, const int* in_sizes, int n_in,
                              void* d_out, int out_size) {
    const float* x     = (const float*)d_in[0];
    const int*   ei    = (const int*)d_in[1];      // JAX x64 disabled -> int32
    const float* W1    = (const float*)d_in[2];
    const float* asrc1 = (const float*)d_in[3];
    const float* adst1 = (const float*)d_in[4];
    const float* b1    = (const float*)d_in[5];
    const float* W2    = (const float*)d_in[6];
    const float* asrc2 = (const float*)d_in[7];
    const float* adst2 = (const float*)d_in[8];
    const float* b2    = (const float*)d_in[9];
    float* out = (float*)d_out;

    int M = in_sizes[0] / F_IN;        // 100000
    int E = in_sizes[1] / 2;           // 1600000
    const int* src = ei;
    const int* dst = ei + E;
    int NB = (M + SCAN_B - 1) / SCAN_B;

    // One-time host-side resources (same GPU work every call).
    static cudaStream_t s2 = nullptr;
    static cudaEvent_t evFork = nullptr, evJoin = nullptr;
    if (s2 == nullptr) {
        cudaStreamCreateWithFlags(&s2, cudaStreamNonBlocking);
        cudaEventCreateWithFlags(&evFork, cudaEventDisableTiming);
        cudaEventCreateWithFlags(&evJoin, cudaEventDisableTiming);
    }

    // Fork: CSR build on s2, GEMM1 on main stream (independent work).
    cudaEventRecord(evFork, 0);
    cudaStreamWaitEvent(s2, evFork, 0);

    zero_counts_kernel<<<(M + 255) / 256, 256, 0, s2>>>(M);
    hist_kernel<<<(E + 255) / 256, 256, 0, s2>>>(dst, E);
    scan_sums_kernel<<<NB, SCAN_B, 0, s2>>>(M);
    scan_offsets_kernel<<<1, SCAN_B, 0, s2>>>(NB, M);
    scan_apply_kernel<<<NB, SCAN_B, 0, s2>>>(M);
    scatter_kernel<<<(E + 255) / 256, 256, 0, s2>>>(src, dst, E);
    cudaEventRecord(evJoin, s2);

    {
        dim3 grid(D1 / TN, (M + TM - 1) / TM);
        gemm1_kernel<<<grid, 256>>>(x, W1, asrc1, adst1, M);
    }

    // Join: aggregate1 needs both CSR and h1/scores.
    cudaStreamWaitEvent(0, evJoin, 0);

    aggregate1_kernel<<<(M * 64 + 255) / 256, 256>>>(b1, M);

    // Layer 2
    gemm2_kernel<<<(M + 127) / 128, 256>>>(W2, asrc2, adst2, M);
    aggregate2_kernel<<<(M * 32 + 255) / 256, 256>>>(b2, out, M);
}

// round 9
// speedup vs baseline: 1.1353x; 1.0102x over previous
#include <cuda_runtime.h>
#include <cuda_bf16.h>
#include <float.h>

#define NNODES 100000
#define F_IN   128
#define D1     256      // 8 heads * 32
#define HEADS  8
#define NCLS   40
#define NEG    0.2f
#define EMAX   1600000
#define SCAN_B 1024

// ---------------- scratch (device globals; no allocation allowed) ----------
__device__ __align__(16) float g_h1[NNODES * D1];              // x @ W1 (fp32)
__device__ __align__(16) __nv_bfloat16 g_h1b[NNODES * D1];     // bf16 copy for gather
__device__ __align__(16) float g_h2[NNODES * D1];              // layer-1 output
__device__ float g_ssrc1[NNODES * HEADS];
__device__ float g_sdst1[NNODES * HEADS];
__device__ float g_pself1[NNODES * HEADS];
__device__ __align__(16) float g_h3[NNODES * NCLS];            // h2 @ W2
__device__ float g_ssrc2[NNODES];
__device__ float g_sdst2[NNODES];
__device__ float g_pself2[NNODES];
// CSR (dst-binned edges)
__device__ int g_counts[NNODES];
__device__ int g_rowptr[NNODES + 1];
__device__ int g_cursor[NNODES];
__device__ int g_csr_src[EMAX];
__device__ int g_bsum[(NNODES + SCAN_B - 1) / SCAN_B];
__device__ int g_boff[(NNODES + SCAN_B - 1) / SCAN_B];

__device__ __forceinline__ float lrelu(float v) { return v >= 0.f ? v : NEG * v; }

// ======================= CSR build ==========================================
__global__ __launch_bounds__(256) void zero_counts_kernel(int n) {
    int i = blockIdx.x * blockDim.x + threadIdx.x;
    if (i < n) g_counts[i] = 0;
}

__global__ __launch_bounds__(256) void hist_kernel(const int* __restrict__ dst, int E) {
    int e = blockIdx.x * blockDim.x + threadIdx.x;
    if (e < E) atomicAdd(&g_counts[dst[e]], 1);
}

__global__ __launch_bounds__(SCAN_B) void scan_sums_kernel(int n) {
    __shared__ int ws[32];
    int i = blockIdx.x * SCAN_B + threadIdx.x;
    int v = (i < n) ? g_counts[i] : 0;
    int lane = threadIdx.x & 31, w = threadIdx.x >> 5;
    int s = v;
#pragma unroll
    for (int o = 16; o; o >>= 1) s += __shfl_xor_sync(0xffffffffu, s, o);
    if (lane == 0) ws[w] = s;
    __syncthreads();
    if (w == 0) {
        int t = ws[lane];
#pragma unroll
        for (int o = 16; o; o >>= 1) t += __shfl_xor_sync(0xffffffffu, t, o);
        if (lane == 0) g_bsum[blockIdx.x] = t;
    }
}

__global__ __launch_bounds__(SCAN_B) void scan_offsets_kernel(int nb, int n) {
    __shared__ int ws[32];
    int lane = threadIdx.x & 31, w = threadIdx.x >> 5;
    int v = (threadIdx.x < nb) ? g_bsum[threadIdx.x] : 0;
    int x = v;
#pragma unroll
    for (int o = 1; o < 32; o <<= 1) {
        int y = __shfl_up_sync(0xffffffffu, x, o);
        if (lane >= o) x += y;
    }
    if (lane == 31) ws[w] = x;
    __syncthreads();
    if (w == 0) {
        int s = ws[lane];
#pragma unroll
        for (int o = 1; o < 32; o <<= 1) {
            int y = __shfl_up_sync(0xffffffffu, s, o);
            if (lane >= o) s += y;
        }
        ws[lane] = s;
    }
    __syncthreads();
    int incl = x + (w > 0 ? ws[w - 1] : 0);
    if (threadIdx.x < nb) g_boff[threadIdx.x] = incl - v;
    if (threadIdx.x == nb - 1) g_rowptr[n] = incl;
}

__global__ __launch_bounds__(SCAN_B) void scan_apply_kernel(int n) {
    __shared__ int ws[32];
    int i = blockIdx.x * SCAN_B + threadIdx.x;
    int v = (i < n) ? g_counts[i] : 0;
    int lane = threadIdx.x & 31, w = threadIdx.x >> 5;
    int x = v;
#pragma unroll
    for (int o = 1; o < 32; o <<= 1) {
        int y = __shfl_up_sync(0xffffffffu, x, o);
        if (lane >= o) x += y;
    }
    if (lane == 31) ws[w] = x;
    __syncthreads();
    if (w == 0) {
        int s = ws[lane];
#pragma unroll
        for (int o = 1; o < 32; o <<= 1) {
            int y = __shfl_up_sync(0xffffffffu, s, o);
            if (lane >= o) s += y;
        }
        ws[lane] = s;
    }
    __syncthreads();
    int excl = x - v + (w > 0 ? ws[w - 1] : 0) + g_boff[blockIdx.x];
    if (i < n) { g_rowptr[i] = excl; g_cursor[i] = excl; }
}

__global__ __launch_bounds__(256) void scatter_kernel(const int* __restrict__ src,
                                                      const int* __restrict__ dst, int E) {
    int e = blockIdx.x * blockDim.x + threadIdx.x;
    if (e >= E) return;
    int pos = atomicAdd(&g_cursor[dst[e]], 1);
    g_csr_src[pos] = src[e];
}

// ======== GEMM1 + fused scores: h1 = x@W1 (fp32 + bf16 copy) ================
#define TM 64
#define TN 64
#define TK 16
#define APAD 4

__global__ __launch_bounds__(256) void gemm1_kernel(const float* __restrict__ A,
                                                    const float* __restrict__ B,
                                                    const float* __restrict__ asrc,
                                                    const float* __restrict__ adst,
                                                    int M) {
    __shared__ float As[TK][TM + APAD];
    __shared__ float Bs[TK][TN + APAD];
    __shared__ float sS[TM][2];
    __shared__ float sD[TM][2];
    int tid = threadIdx.x;
    int tx = tid & 15, ty = tid >> 4;
    int rowBase = blockIdx.y * TM;
    int colBase = blockIdx.x * TN;
    float acc[4][4] = {};

    if (tid < TM) { sS[tid][0] = 0.f; sS[tid][1] = 0.f; sD[tid][0] = 0.f; sD[tid][1] = 0.f; }

    for (int k0 = 0; k0 < F_IN; k0 += TK) {
        {
            int r  = tid >> 2;
            int kg = (tid & 3) * 4;
            float4 v = make_float4(0.f, 0.f, 0.f, 0.f);
            int gr = rowBase + r;
            if (gr < M) v = *(const float4*)&A[(size_t)gr * F_IN + k0 + kg];
            As[kg + 0][r] = v.x; As[kg + 1][r] = v.y;
            As[kg + 2][r] = v.z; As[kg + 3][r] = v.w;
        }
        {
            int kk = tid >> 4;
            int c  = (tid & 15) * 4;
            float4 v = *(const float4*)&B[(size_t)(k0 + kk) * D1 + colBase + c];
            Bs[kk][c + 0] = v.x; Bs[kk][c + 1] = v.y;
            Bs[kk][c + 2] = v.z; Bs[kk][c + 3] = v.w;
        }
        __syncthreads();
#pragma unroll
        for (int kk = 0; kk < TK; kk++) {
            float a0 = As[kk][ty * 4 + 0], a1 = As[kk][ty * 4 + 1];
            float a2 = As[kk][ty * 4 + 2], a3 = As[kk][ty * 4 + 3];
            float b0 = Bs[kk][tx * 4 + 0], b1 = Bs[kk][tx * 4 + 1];
            float b2 = Bs[kk][tx * 4 + 2], b3 = Bs[kk][tx * 4 + 3];
            acc[0][0] += a0 * b0; acc[0][1] += a0 * b1; acc[0][2] += a0 * b2; acc[0][3] += a0 * b3;
            acc[1][0] += a1 * b0; acc[1][1] += a1 * b1; acc[1][2] += a1 * b2; acc[1][3] += a1 * b3;
            acc[2][0] += a2 * b0; acc[2][1] += a2 * b1; acc[2][2] += a2 * b2; acc[2][3] += a2 * b3;
            acc[3][0] += a3 * b0; acc[3][1] += a3 * b1; acc[3][2] += a3 * b2; acc[3][3] += a3 * b3;
        }
        __syncthreads();
    }
#pragma unroll
    for (int i = 0; i < 4; i++) {
        int gr = rowBase + ty * 4 + i;
        if (gr < M) {
            float4 o = make_float4(acc[i][0], acc[i][1], acc[i][2], acc[i][3]);
            size_t off = (size_t)gr * D1 + colBase + tx * 4;
            *(float4*)&g_h1[off] = o;
            __nv_bfloat162 p0 = __floats2bfloat162_rn(acc[i][0], acc[i][1]);
            __nv_bfloat162 p1 = __floats2bfloat162_rn(acc[i][2], acc[i][3]);
            uint2 packed;
            packed.x = *reinterpret_cast<unsigned int*>(&p0);
            packed.y = *reinterpret_cast<unsigned int*>(&p1);
            *(uint2*)&g_h1b[off] = packed;
        }
    }
    float4 av = *(const float4*)&asrc[colBase + tx * 4];
    float4 dv = *(const float4*)&adst[colBase + tx * 4];
    int hh = tx >> 3;
#pragma unroll
    for (int i = 0; i < 4; i++) {
        float ps = acc[i][0]*av.x + acc[i][1]*av.y + acc[i][2]*av.z + acc[i][3]*av.w;
        float pd = acc[i][0]*dv.x + acc[i][1]*dv.y + acc[i][2]*dv.z + acc[i][3]*dv.w;
        atomicAdd(&sS[ty * 4 + i][hh], ps);
        atomicAdd(&sD[ty * 4 + i][hh], pd);
    }
    __syncthreads();
    if (tid < 2 * TM) {
        int row = tid >> 1, h2i = tid & 1;
        int gr = rowBase + row;
        if (gr < M) {
            int head = blockIdx.x * 2 + h2i;
            float ps = sS[row][h2i], pd = sD[row][h2i];
            g_ssrc1[gr * HEADS + head] = ps;
            g_sdst1[gr * HEADS + head] = pd;
            g_pself1[gr * HEADS + head] = __expf(lrelu(ps + pd));
        }
    }
}

// ======== aggregate1: 2 warps/node, bf16 gather, fp32 accumulate ============
__global__ __launch_bounds__(256) void aggregate1_kernel(const float* __restrict__ b1, int M) {
    int gw   = (blockIdx.x * blockDim.x + threadIdx.x) >> 5;
    int node = gw >> 1;
    int half = gw & 1;
    int lane = threadIdx.x & 31;
    if (node >= M) return;
    int ch = half * 128 + lane * 4;          // 4 channels per lane
    int h  = ch >> 5;
    float sdst_h = g_sdst1[node * HEADS + h];
    float pself  = g_pself1[node * HEADS + h];
    size_t nb = (size_t)node * D1 + ch;
    float4 a = *(const float4*)&g_h1[nb];    // self term in fp32
    float c0 = a.x * pself, c1 = a.y * pself, c2 = a.z * pself, c3 = a.w * pself;
    float denom = pself;
    int beg = g_rowptr[node], end = g_rowptr[node + 1];
    int i = beg;
    for (; i + 2 <= end; i += 2) {
        int s0 = __ldg(&g_csr_src[i]);
        int s1 = __ldg(&g_csr_src[i + 1]);
        float p0 = __expf(lrelu(__ldg(&g_ssrc1[s0 * HEADS + h]) + sdst_h));
        float p1 = __expf(lrelu(__ldg(&g_ssrc1[s1 * HEADS + h]) + sdst_h));
        uint2 r0 = *(const uint2*)&g_h1b[(size_t)s0 * D1 + ch];
        uint2 r1 = *(const uint2*)&g_h1b[(size_t)s1 * D1 + ch];
        float2 v0a = __bfloat1622float2(*reinterpret_cast<__nv_bfloat162*>(&r0.x));
        float2 v0b = __bfloat1622float2(*reinterpret_cast<__nv_bfloat162*>(&r0.y));
        float2 v1a = __bfloat1622float2(*reinterpret_cast<__nv_bfloat162*>(&r1.x));
        float2 v1b = __bfloat1622float2(*reinterpret_cast<__nv_bfloat162*>(&r1.y));
        c0 += v0a.x * p0 + v1a.x * p1;
        c1 += v0a.y * p0 + v1a.y * p1;
        c2 += v0b.x * p0 + v1b.x * p1;
        c3 += v0b.y * p0 + v1b.y * p1;
        denom += p0 + p1;
    }
    if (i < end) {
        int s = __ldg(&g_csr_src[i]);
        float p = __expf(lrelu(__ldg(&g_ssrc1[s * HEADS + h]) + sdst_h));
        uint2 r = *(const uint2*)&g_h1b[(size_t)s * D1 + ch];
        float2 va = __bfloat1622float2(*reinterpret_cast<__nv_bfloat162*>(&r.x));
        float2 vb = __bfloat1622float2(*reinterpret_cast<__nv_bfloat162*>(&r.y));
        c0 += va.x * p; c1 += va.y * p; c2 += vb.x * p; c3 += vb.y * p;
        denom += p;
    }
    float inv = __frcp_rn(denom);
    float4 bb = *(const float4*)&b1[ch];
    float4 o;
    o.x = fmaxf(c0 * inv + bb.x, 0.f);
    o.y = fmaxf(c1 * inv + bb.y, 0.f);
    o.z = fmaxf(c2 * inv + bb.z, 0.f);
    o.w = fmaxf(c3 * inv + bb.w, 0.f);
    *(float4*)&g_h2[nb] = o;
}

// ======== GEMM2 + fused scores2: h3 = h2@W2; s_src2/s_dst2/p_self2 =========
__global__ __launch_bounds__(256) void gemm2_kernel(const float* __restrict__ B,
                                                    const float* __restrict__ asrc,
                                                    const float* __restrict__ adst,
                                                    int M) {
    __shared__ float Bs[D1 * NCLS];  // 40 KB
    for (int i = threadIdx.x; i < D1 * NCLS; i += 256) Bs[i] = B[i];
    __syncthreads();
    int warp = threadIdx.x >> 5, lane = threadIdx.x & 31;
    float as0 = asrc[lane], ad0 = adst[lane];
    float as1 = (lane < 8) ? asrc[32 + lane] : 0.f;
    float ad1 = (lane < 8) ? adst[32 + lane] : 0.f;
    const int RPW = 16;
    int rowBase = (blockIdx.x * 8 + warp) * RPW;
    for (int i = 0; i < RPW; i++) {
        int row = rowBase + i;
        if (row >= M) return;
        const float* a = &g_h2[(size_t)row * D1];
        float acc0 = 0.f, acc1 = 0.f;
#pragma unroll 4
        for (int k = 0; k < D1; k += 4) {
            float4 av = *(const float4*)(a + k);   // broadcast load
            acc0 += av.x * Bs[(k + 0) * NCLS + lane];
            acc0 += av.y * Bs[(k + 1) * NCLS + lane];
            acc0 += av.z * Bs[(k + 2) * NCLS + lane];
            acc0 += av.w * Bs[(k + 3) * NCLS + lane];
            if (lane < 8) {
                acc1 += av.x * Bs[(k + 0) * NCLS + 32 + lane];
                acc1 += av.y * Bs[(k + 1) * NCLS + 32 + lane];
                acc1 += av.z * Bs[(k + 2) * NCLS + 32 + lane];
                acc1 += av.w * Bs[(k + 3) * NCLS + 32 + lane];
            }
        }
        g_h3[(size_t)row * NCLS + lane] = acc0;
        if (lane < 8) g_h3[(size_t)row * NCLS + 32 + lane] = acc1;
        float ps = acc0 * as0 + ((lane < 8) ? acc1 * as1 : 0.f);
        float pd = acc0 * ad0 + ((lane < 8) ? acc1 * ad1 : 0.f);
#pragma unroll
        for (int o = 16; o; o >>= 1) {
            ps += __shfl_xor_sync(0xffffffffu, ps, o);
            pd += __shfl_xor_sync(0xffffffffu, pd, o);
        }
        if (lane == 0) {
            g_ssrc2[row] = ps;
            g_sdst2[row] = pd;
            g_pself2[row] = __expf(lrelu(ps + pd));
        }
    }
}

// ======== aggregate2: node-per-warp, CSR, unroll-2, fused log_softmax ======
__global__ __launch_bounds__(256) void aggregate2_kernel(const float* __restrict__ b2,
                                                         float* __restrict__ out, int M) {
    int wid  = (blockIdx.x * blockDim.x + threadIdx.x) >> 5;
    int lane = threadIdx.x & 31;
    if (wid >= M) return;
    float sdst = g_sdst2[wid];
    float pself = g_pself2[wid];
    size_t nb = (size_t)wid * NCLS;
    float v0 = g_h3[nb + lane] * pself;
    float v1 = (lane < 8) ? g_h3[nb + 32 + lane] * pself : 0.f;
    float denom = pself;
    int beg = g_rowptr[wid], end = g_rowptr[wid + 1];
    int i = beg;
    for (; i + 2 <= end; i += 2) {
        int s0 = __ldg(&g_csr_src[i]);
        int s1 = __ldg(&g_csr_src[i + 1]);
        float p0 = __expf(lrelu(__ldg(&g_ssrc2[s0]) + sdst));
        float p1 = __expf(lrelu(__ldg(&g_ssrc2[s1]) + sdst));
        size_t sb0 = (size_t)s0 * NCLS, sb1 = (size_t)s1 * NCLS;
        v0 += p0 * g_h3[sb0 + lane] + p1 * g_h3[sb1 + lane];
        if (lane < 8) v1 += p0 * g_h3[sb0 + 32 + lane] + p1 * g_h3[sb1 + 32 + lane];
        denom += p0 + p1;
    }
    if (i < end) {
        int s = __ldg(&g_csr_src[i]);
        float p = __expf(lrelu(__ldg(&g_ssrc2[s]) + sdst));
        size_t sb = (size_t)s * NCLS;
        v0 += p * g_h3[sb + lane];
        if (lane < 8) v1 += p * g_h3[sb + 32 + lane];
        denom += p;
    }
    float inv = __frcp_rn(denom);
    float z0 = v0 * inv + b2[lane];
    float z1 = (lane < 8) ? (v1 * inv + b2[32 + lane]) : -FLT_MAX;
    float m = fmaxf(z0, z1);
#pragma unroll
    for (int o = 16; o; o >>= 1) m = fmaxf(m, __shfl_xor_sync(0xffffffffu, m, o));
    float s = expf(z0 - m) + ((lane < 8) ? expf(z1 - m) : 0.f);
#pragma unroll
    for (int o = 16; o; o >>= 1) s += __shfl_xor_sync(0xffffffffu, s, o);
    float ls = logf(s);
    out[nb + lane] = z0 - m - ls;
    if (lane < 8) out[nb + 32 + lane] = z1 - m - ls;
}

// ---------------------------------------------------------------------------
extern "C" void kernel_launch(void* const* d_in, const int* in_sizes, int n_in,
                              void* d_out, int out_size) {
    const float* x     = (const float*)d_in[0];
    const int*   ei    = (const int*)d_in[1];      // JAX x64 disabled -> int32
    const float* W1    = (const float*)d_in[2];
    const float* asrc1 = (const float*)d_in[3];
    const float* adst1 = (const float*)d_in[4];
    const float* b1    = (const float*)d_in[5];
    const float* W2    = (const float*)d_in[6];
    const float* asrc2 = (const float*)d_in[7];
    const float* adst2 = (const float*)d_in[8];
    const float* b2    = (const float*)d_in[9];
    float* out = (float*)d_out;

    int M = in_sizes[0] / F_IN;        // 100000
    int E = in_sizes[1] / 2;           // 1600000
    const int* src = ei;
    const int* dst = ei + E;
    int NB = (M + SCAN_B - 1) / SCAN_B;

    // One-time host-side resources (same GPU work every call).
    static cudaStream_t s2 = nullptr;
    static cudaEvent_t evFork = nullptr, evJoin = nullptr;
    if (s2 == nullptr) {
        cudaStreamCreateWithFlags(&s2, cudaStreamNonBlocking);
        cudaEventCreateWithFlags(&evFork, cudaEventDisableTiming);
        cudaEventCreateWithFlags(&evJoin, cudaEventDisableTiming);
    }

    // Fork: CSR build on s2, GEMM1 on main stream (independent work).
    cudaEventRecord(evFork, 0);
    cudaStreamWaitEvent(s2, evFork, 0);

    zero_counts_kernel<<<(M + 255) / 256, 256, 0, s2>>>(M);
    hist_kernel<<<(E + 255) / 256, 256, 0, s2>>>(dst, E);
    scan_sums_kernel<<<NB, SCAN_B, 0, s2>>>(M);
    scan_offsets_kernel<<<1, SCAN_B, 0, s2>>>(NB, M);
    scan_apply_kernel<<<NB, SCAN_B, 0, s2>>>(M);
    scatter_kernel<<<(E + 255) / 256, 256, 0, s2>>>(src, dst, E);
    cudaEventRecord(evJoin, s2);

    {
        dim3 grid(D1 / TN, (M + TM - 1) / TM);
        gemm1_kernel<<<grid, 256>>>(x, W1, asrc1, adst1, M);
    }

    // Join: aggregate1 needs both CSR and h1/scores.
    cudaStreamWaitEvent(0, evJoin, 0);

    aggregate1_kernel<<<(M * 64 + 255) / 256, 256>>>(b1, M);

    // Layer 2
    gemm2_kernel<<<(M + 127) / 128, 256>>>(W2, asrc2, adst2, M);
    aggregate2_kernel<<<(M * 32 + 255) / 256, 256>>>(b2, out, M);
}

// round 10
// speedup vs baseline: 1.2780x; 1.1257x over previous
#include <cuda_runtime.h>
#include <cuda_bf16.h>
#include <float.h>

#define NNODES 100000
#define F_IN   128
#define D1     256      // 8 heads * 32
#define HEADS  8
#define NCLS   40
#define NEG    0.2f
#define EMAX   1600000
#define SCAN_B 1024

// ---------------- scratch (device globals; no allocation allowed) ----------
__device__ __align__(16) float g_h1[NNODES * D1];              // x @ W1 (fp32)
__device__ __align__(16) __nv_bfloat16 g_h1b[NNODES * D1];     // bf16 copy for gather
__device__ __align__(16) float g_h2[NNODES * D1];              // layer-1 output
__device__ float g_ssrc1[NNODES * HEADS];
__device__ float g_sdst1[NNODES * HEADS];
__device__ float g_pself1[NNODES * HEADS];
__device__ __align__(16) float g_h3[NNODES * NCLS];            // h2 @ W2
__device__ float g_ssrc2[NNODES];
__device__ float g_sdst2[NNODES];
__device__ float g_pself2[NNODES];
// CSR (dst-binned edges)
__device__ int g_counts[NNODES];
__device__ int g_rowptr[NNODES + 1];
__device__ int g_cursor[NNODES];
__device__ int g_csr_src[EMAX];
__device__ int g_bsum[(NNODES + SCAN_B - 1) / SCAN_B];
__device__ int g_boff[(NNODES + SCAN_B - 1) / SCAN_B];

__device__ __forceinline__ float lrelu(float v) { return v >= 0.f ? v : NEG * v; }
__device__ __forceinline__ unsigned f2tf32(float f) {
    unsigned u;
    asm("cvt.rna.tf32.f32 %0, %1;" : "=r"(u) : "f"(f));
    return u;
}

// ======================= CSR build ==========================================
__global__ __launch_bounds__(256) void zero_counts_kernel(int n) {
    int i = blockIdx.x * blockDim.x + threadIdx.x;
    if (i < n) g_counts[i] = 0;
}

__global__ __launch_bounds__(256) void hist_kernel(const int* __restrict__ dst, int E) {
    int e = blockIdx.x * blockDim.x + threadIdx.x;
    if (e < E) atomicAdd(&g_counts[dst[e]], 1);
}

__global__ __launch_bounds__(SCAN_B) void scan_sums_kernel(int n) {
    __shared__ int ws[32];
    int i = blockIdx.x * SCAN_B + threadIdx.x;
    int v = (i < n) ? g_counts[i] : 0;
    int lane = threadIdx.x & 31, w = threadIdx.x >> 5;
    int s = v;
#pragma unroll
    for (int o = 16; o; o >>= 1) s += __shfl_xor_sync(0xffffffffu, s, o);
    if (lane == 0) ws[w] = s;
    __syncthreads();
    if (w == 0) {
        int t = ws[lane];
#pragma unroll
        for (int o = 16; o; o >>= 1) t += __shfl_xor_sync(0xffffffffu, t, o);
        if (lane == 0) g_bsum[blockIdx.x] = t;
    }
}

__global__ __launch_bounds__(SCAN_B) void scan_offsets_kernel(int nb, int n) {
    __shared__ int ws[32];
    int lane = threadIdx.x & 31, w = threadIdx.x >> 5;
    int v = (threadIdx.x < nb) ? g_bsum[threadIdx.x] : 0;
    int x = v;
#pragma unroll
    for (int o = 1; o < 32; o <<= 1) {
        int y = __shfl_up_sync(0xffffffffu, x, o);
        if (lane >= o) x += y;
    }
    if (lane == 31) ws[w] = x;
    __syncthreads();
    if (w == 0) {
        int s = ws[lane];
#pragma unroll
        for (int o = 1; o < 32; o <<= 1) {
            int y = __shfl_up_sync(0xffffffffu, s, o);
            if (lane >= o) s += y;
        }
        ws[lane] = s;
    }
    __syncthreads();
    int incl = x + (w > 0 ? ws[w - 1] : 0);
    if (threadIdx.x < nb) g_boff[threadIdx.x] = incl - v;
    if (threadIdx.x == nb - 1) g_rowptr[n] = incl;
}

__global__ __launch_bounds__(SCAN_B) void scan_apply_kernel(int n) {
    __shared__ int ws[32];
    int i = blockIdx.x * SCAN_B + threadIdx.x;
    int v = (i < n) ? g_counts[i] : 0;
    int lane = threadIdx.x & 31, w = threadIdx.x >> 5;
    int x = v;
#pragma unroll
    for (int o = 1; o < 32; o <<= 1) {
        int y = __shfl_up_sync(0xffffffffu, x, o);
        if (lane >= o) x += y;
    }
    if (lane == 31) ws[w] = x;
    __syncthreads();
    if (w == 0) {
        int s = ws[lane];
#pragma unroll
        for (int o = 1; o < 32; o <<= 1) {
            int y = __shfl_up_sync(0xffffffffu, s, o);
            if (lane >= o) s += y;
        }
        ws[lane] = s;
    }
    __syncthreads();
    int excl = x - v + (w > 0 ? ws[w - 1] : 0) + g_boff[blockIdx.x];
    if (i < n) { g_rowptr[i] = excl; g_cursor[i] = excl; }
}

__global__ __launch_bounds__(256) void scatter_kernel(const int* __restrict__ src,
                                                      const int* __restrict__ dst, int E) {
    int e = blockIdx.x * blockDim.x + threadIdx.x;
    if (e >= E) return;
    int pos = atomicAdd(&g_cursor[dst[e]], 1);
    g_csr_src[pos] = src[e];
}

// ======== GEMM1 via tf32 mma.sync: h1[M,256] = x[M,128] @ W1[128,256] =======
// Block 64x64, 256 thr = 8 warps (2m x 4n), warp tile 32x16 (2 m16 x 2 n8).
__global__ __launch_bounds__(256) void gemm1_tf32_kernel(const float* __restrict__ A,
                                                         const float* __restrict__ B,
                                                         int M) {
    __shared__ unsigned As[64][36];   // 32 k-chunk + pad4  (9.2 KB)
    __shared__ unsigned Bs[128][72];  // 64 n + pad8        (36.9 KB)
    int tid = threadIdx.x;
    int warp = tid >> 5, lane = tid & 31;
    int q = lane >> 2, r4 = lane & 3;
    int rowBase = blockIdx.y * 64;
    int colBase = blockIdx.x * 64;
    int wm = (warp >> 2) * 32;
    int wn = (warp & 3) * 16;

    // Load full B tile (128 x 64) as tf32
    for (int j = tid; j < 2048; j += 256) {        // 2048 float4
        int k = j >> 4;
        int n4 = (j & 15) * 4;
        float4 v = *(const float4*)&B[(size_t)k * D1 + colBase + n4];
        uint4 t;
        t.x = f2tf32(v.x); t.y = f2tf32(v.y); t.z = f2tf32(v.z); t.w = f2tf32(v.w);
        *(uint4*)&Bs[k][n4] = t;
    }

    float c[2][2][4] = {};
    for (int kc = 0; kc < 4; kc++) {
        // Load A chunk (64 rows x 32 k) as tf32
        for (int j = tid; j < 512; j += 256) {     // 512 float4
            int r = j >> 3;
            int k4 = (j & 7) * 4;
            int gr = rowBase + r;
            float4 v = make_float4(0.f, 0.f, 0.f, 0.f);
            if (gr < M) v = *(const float4*)&A[(size_t)gr * F_IN + kc * 32 + k4];
            uint4 t;
            t.x = f2tf32(v.x); t.y = f2tf32(v.y); t.z = f2tf32(v.z); t.w = f2tf32(v.w);
            *(uint4*)&As[r][k4] = t;
        }
        __syncthreads();
#pragma unroll
        for (int ks = 0; ks < 4; ks++) {
            int kk = ks * 8;
            unsigned a[2][4], b[2][2];
#pragma unroll
            for (int mt = 0; mt < 2; mt++) {
                int rr = wm + mt * 16 + q;
                a[mt][0] = As[rr][kk + r4];
                a[mt][1] = As[rr + 8][kk + r4];
                a[mt][2] = As[rr][kk + r4 + 4];
                a[mt][3] = As[rr + 8][kk + r4 + 4];
            }
#pragma unroll
            for (int nt = 0; nt < 2; nt++) {
                int cc = wn + nt * 8 + q;
                b[nt][0] = Bs[kc * 32 + kk + r4][cc];
                b[nt][1] = Bs[kc * 32 + kk + r4 + 4][cc];
            }
#pragma unroll
            for (int mt = 0; mt < 2; mt++)
#pragma unroll
                for (int nt = 0; nt < 2; nt++) {
                    asm volatile(
                        "mma.sync.aligned.m16n8k8.row.col.f32.tf32.tf32.f32 "
                        "{%0,%1,%2,%3}, {%4,%5,%6,%7}, {%8,%9}, {%0,%1,%2,%3};"
                        : "+f"(c[mt][nt][0]), "+f"(c[mt][nt][1]),
                          "+f"(c[mt][nt][2]), "+f"(c[mt][nt][3])
                        : "r"(a[mt][0]), "r"(a[mt][1]), "r"(a[mt][2]), "r"(a[mt][3]),
                          "r"(b[nt][0]), "r"(b[nt][1]));
                }
        }
        __syncthreads();
    }
    // Epilogue: c0,c1 -> (row, col..col+1); c2,c3 -> (row+8, col..col+1)
#pragma unroll
    for (int mt = 0; mt < 2; mt++) {
        int r0 = rowBase + wm + mt * 16 + q;
#pragma unroll
        for (int nt = 0; nt < 2; nt++) {
            int col = colBase + wn + nt * 8 + r4 * 2;
            if (r0 < M) {
                float2 w0 = make_float2(c[mt][nt][0], c[mt][nt][1]);
                *(float2*)&g_h1[(size_t)r0 * D1 + col] = w0;
            }
            if (r0 + 8 < M) {
                float2 w1 = make_float2(c[mt][nt][2], c[mt][nt][3]);
                *(float2*)&g_h1[(size_t)(r0 + 8) * D1 + col] = w1;
            }
        }
    }
}

// ======== scores1 + bf16 copy: one pass over h1 =============================
__global__ __launch_bounds__(256) void scores1_kernel(const float* __restrict__ asrc,
                                                      const float* __restrict__ adst,
                                                      int n) {
    int wid  = (blockIdx.x * blockDim.x + threadIdx.x) >> 5;
    int lane = threadIdx.x & 31;
    if (wid >= n) return;
    size_t base = (size_t)wid * D1 + lane * 8;
    float4 v0 = *(const float4*)&g_h1[base];
    float4 v1 = *(const float4*)&g_h1[base + 4];
    float4 a0 = *(const float4*)&asrc[lane * 8];
    float4 a1 = *(const float4*)&asrc[lane * 8 + 4];
    float4 d0 = *(const float4*)&adst[lane * 8];
    float4 d1 = *(const float4*)&adst[lane * 8 + 4];
    float ps = v0.x*a0.x + v0.y*a0.y + v0.z*a0.z + v0.w*a0.w
             + v1.x*a1.x + v1.y*a1.y + v1.z*a1.z + v1.w*a1.w;
    float pd = v0.x*d0.x + v0.y*d0.y + v0.z*d0.z + v0.w*d0.w
             + v1.x*d1.x + v1.y*d1.y + v1.z*d1.z + v1.w*d1.w;
    ps += __shfl_xor_sync(0xffffffffu, ps, 1);
    ps += __shfl_xor_sync(0xffffffffu, ps, 2);
    pd += __shfl_xor_sync(0xffffffffu, pd, 1);
    pd += __shfl_xor_sync(0xffffffffu, pd, 2);
    int h = lane >> 2;
    if ((lane & 3) == 0) {
        g_ssrc1[wid * HEADS + h] = ps;
        g_sdst1[wid * HEADS + h] = pd;
        g_pself1[wid * HEADS + h] = __expf(lrelu(ps + pd));
    }
    // bf16 copy of the row
    __nv_bfloat162 p0 = __floats2bfloat162_rn(v0.x, v0.y);
    __nv_bfloat162 p1 = __floats2bfloat162_rn(v0.z, v0.w);
    __nv_bfloat162 p2 = __floats2bfloat162_rn(v1.x, v1.y);
    __nv_bfloat162 p3 = __floats2bfloat162_rn(v1.z, v1.w);
    uint4 pk;
    pk.x = *reinterpret_cast<unsigned*>(&p0);
    pk.y = *reinterpret_cast<unsigned*>(&p1);
    pk.z = *reinterpret_cast<unsigned*>(&p2);
    pk.w = *reinterpret_cast<unsigned*>(&p3);
    *(uint4*)&g_h1b[base] = pk;
}

// ======== aggregate1: 2 warps/node, bf16 gather, fp32 accumulate ============
__global__ __launch_bounds__(256) void aggregate1_kernel(const float* __restrict__ b1, int M) {
    int gw   = (blockIdx.x * blockDim.x + threadIdx.x) >> 5;
    int node = gw >> 1;
    int half = gw & 1;
    int lane = threadIdx.x & 31;
    if (node >= M) return;
    int ch = half * 128 + lane * 4;          // 4 channels per lane
    int h  = ch >> 5;
    float sdst_h = g_sdst1[node * HEADS + h];
    float pself  = g_pself1[node * HEADS + h];
    size_t nb = (size_t)node * D1 + ch;
    float4 a = *(const float4*)&g_h1[nb];    // self term in fp32
    float c0 = a.x * pself, c1 = a.y * pself, c2 = a.z * pself, c3 = a.w * pself;
    float denom = pself;
    int beg = g_rowptr[node], end = g_rowptr[node + 1];
    int i = beg;
    for (; i + 2 <= end; i += 2) {
        int s0 = __ldg(&g_csr_src[i]);
        int s1 = __ldg(&g_csr_src[i + 1]);
        float p0 = __expf(lrelu(__ldg(&g_ssrc1[s0 * HEADS + h]) + sdst_h));
        float p1 = __expf(lrelu(__ldg(&g_ssrc1[s1 * HEADS + h]) + sdst_h));
        uint2 r0 = *(const uint2*)&g_h1b[(size_t)s0 * D1 + ch];
        uint2 r1 = *(const uint2*)&g_h1b[(size_t)s1 * D1 + ch];
        float2 v0a = __bfloat1622float2(*reinterpret_cast<__nv_bfloat162*>(&r0.x));
        float2 v0b = __bfloat1622float2(*reinterpret_cast<__nv_bfloat162*>(&r0.y));
        float2 v1a = __bfloat1622float2(*reinterpret_cast<__nv_bfloat162*>(&r1.x));
        float2 v1b = __bfloat1622float2(*reinterpret_cast<__nv_bfloat162*>(&r1.y));
        c0 += v0a.x * p0 + v1a.x * p1;
        c1 += v0a.y * p0 + v1a.y * p1;
        c2 += v0b.x * p0 + v1b.x * p1;
        c3 += v0b.y * p0 + v1b.y * p1;
        denom += p0 + p1;
    }
    if (i < end) {
        int s = __ldg(&g_csr_src[i]);
        float p = __expf(lrelu(__ldg(&g_ssrc1[s * HEADS + h]) + sdst_h));
        uint2 r = *(const uint2*)&g_h1b[(size_t)s * D1 + ch];
        float2 va = __bfloat1622float2(*reinterpret_cast<__nv_bfloat162*>(&r.x));
        float2 vb = __bfloat1622float2(*reinterpret_cast<__nv_bfloat162*>(&r.y));
        c0 += va.x * p; c1 += va.y * p; c2 += vb.x * p; c3 += vb.y * p;
        denom += p;
    }
    float inv = __frcp_rn(denom);
    float4 bb = *(const float4*)&b1[ch];
    float4 o;
    o.x = fmaxf(c0 * inv + bb.x, 0.f);
    o.y = fmaxf(c1 * inv + bb.y, 0.f);
    o.z = fmaxf(c2 * inv + bb.z, 0.f);
    o.w = fmaxf(c3 * inv + bb.w, 0.f);
    *(float4*)&g_h2[nb] = o;
}

// ======== GEMM2 + fused scores2: h3 = h2@W2; s_src2/s_dst2/p_self2 =========
__global__ __launch_bounds__(256) void gemm2_kernel(const float* __restrict__ B,
                                                    const float* __restrict__ asrc,
                                                    const float* __restrict__ adst,
                                                    int M) {
    __shared__ float Bs[D1 * NCLS];  // 40 KB
    for (int i = threadIdx.x; i < D1 * NCLS; i += 256) Bs[i] = B[i];
    __syncthreads();
    int warp = threadIdx.x >> 5, lane = threadIdx.x & 31;
    float as0 = asrc[lane], ad0 = adst[lane];
    float as1 = (lane < 8) ? asrc[32 + lane] : 0.f;
    float ad1 = (lane < 8) ? adst[32 + lane] : 0.f;
    const int RPW = 16;
    int rowBase = (blockIdx.x * 8 + warp) * RPW;
    for (int i = 0; i < RPW; i++) {
        int row = rowBase + i;
        if (row >= M) return;
        const float* a = &g_h2[(size_t)row * D1];
        float acc0 = 0.f, acc1 = 0.f;
#pragma unroll 4
        for (int k = 0; k < D1; k += 4) {
            float4 av = *(const float4*)(a + k);   // broadcast load
            acc0 += av.x * Bs[(k + 0) * NCLS + lane];
            acc0 += av.y * Bs[(k + 1) * NCLS + lane];
            acc0 += av.z * Bs[(k + 2) * NCLS + lane];
            acc0 += av.w * Bs[(k + 3) * NCLS + lane];
            if (lane < 8) {
                acc1 += av.x * Bs[(k + 0) * NCLS + 32 + lane];
                acc1 += av.y * Bs[(k + 1) * NCLS + 32 + lane];
                acc1 += av.z * Bs[(k + 2) * NCLS + 32 + lane];
                acc1 += av.w * Bs[(k + 3) * NCLS + 32 + lane];
            }
        }
        g_h3[(size_t)row * NCLS + lane] = acc0;
        if (lane < 8) g_h3[(size_t)row * NCLS + 32 + lane] = acc1;
        float ps = acc0 * as0 + ((lane < 8) ? acc1 * as1 : 0.f);
        float pd = acc0 * ad0 + ((lane < 8) ? acc1 * ad1 : 0.f);
#pragma unroll
        for (int o = 16; o; o >>= 1) {
            ps += __shfl_xor_sync(0xffffffffu, ps, o);
            pd += __shfl_xor_sync(0xffffffffu, pd, o);
        }
        if (lane == 0) {
            g_ssrc2[row] = ps;
            g_sdst2[row] = pd;
            g_pself2[row] = __expf(lrelu(ps + pd));
        }
    }
}

// ======== aggregate2: node-per-warp, CSR, unroll-2, fused log_softmax ======
__global__ __launch_bounds__(256) void aggregate2_kernel(const float* __restrict__ b2,
                                                         float* __restrict__ out, int M) {
    int wid  = (blockIdx.x * blockDim.x + threadIdx.x) >> 5;
    int lane = threadIdx.x & 31;
    if (wid >= M) return;
    float sdst = g_sdst2[wid];
    float pself = g_pself2[wid];
    size_t nb = (size_t)wid * NCLS;
    float v0 = g_h3[nb + lane] * pself;
    float v1 = (lane < 8) ? g_h3[nb + 32 + lane] * pself : 0.f;
    float denom = pself;
    int beg = g_rowptr[wid], end = g_rowptr[wid + 1];
    int i = beg;
    for (; i + 2 <= end; i += 2) {
        int s0 = __ldg(&g_csr_src[i]);
        int s1 = __ldg(&g_csr_src[i + 1]);
        float p0 = __expf(lrelu(__ldg(&g_ssrc2[s0]) + sdst));
        float p1 = __expf(lrelu(__ldg(&g_ssrc2[s1]) + sdst));
        size_t sb0 = (size_t)s0 * NCLS, sb1 = (size_t)s1 * NCLS;
        v0 += p0 * g_h3[sb0 + lane] + p1 * g_h3[sb1 + lane];
        if (lane < 8) v1 += p0 * g_h3[sb0 + 32 + lane] + p1 * g_h3[sb1 + 32 + lane];
        denom += p0 + p1;
    }
    if (i < end) {
        int s = __ldg(&g_csr_src[i]);
        float p = __expf(lrelu(__ldg(&g_ssrc2[s]) + sdst));
        size_t sb = (size_t)s * NCLS;
        v0 += p * g_h3[sb + lane];
        if (lane < 8) v1 += p * g_h3[sb + 32 + lane];
        denom += p;
    }
    float inv = __frcp_rn(denom);
    float z0 = v0 * inv + b2[lane];
    float z1 = (lane < 8) ? (v1 * inv + b2[32 + lane]) : -FLT_MAX;
    float m = fmaxf(z0, z1);
#pragma unroll
    for (int o = 16; o; o >>= 1) m = fmaxf(m, __shfl_xor_sync(0xffffffffu, m, o));
    float s = expf(z0 - m) + ((lane < 8) ? expf(z1 - m) : 0.f);
#pragma unroll
    for (int o = 16; o; o >>= 1) s += __shfl_xor_sync(0xffffffffu, s, o);
    float ls = logf(s);
    out[nb + lane] = z0 - m - ls;
    if (lane < 8) out[nb + 32 + lane] = z1 - m - ls;
}

// ---------------------------------------------------------------------------
extern "C" void kernel_launch(void* const* d_in, const int* in_sizes, int n_in,
                              void* d_out, int out_size) {
    const float* x     = (const float*)d_in[0];
    const int*   ei    = (const int*)d_in[1];      // JAX x64 disabled -> int32
    const float* W1    = (const float*)d_in[2];
    const float* asrc1 = (const float*)d_in[3];
    const float* adst1 = (const float*)d_in[4];
    const float* b1    = (const float*)d_in[5];
    const float* W2    = (const float*)d_in[6];
    const float* asrc2 = (const float*)d_in[7];
    const float* adst2 = (const float*)d_in[8];
    const float* b2    = (const float*)d_in[9];
    float* out = (float*)d_out;

    int M = in_sizes[0] / F_IN;        // 100000
    int E = in_sizes[1] / 2;           // 1600000
    const int* src = ei;
    const int* dst = ei + E;
    int NB = (M + SCAN_B - 1) / SCAN_B;

    // One-time host-side resources (same GPU work every call).
    static cudaStream_t s2 = nullptr;
    static cudaEvent_t evFork = nullptr, evJoin = nullptr;
    if (s2 == nullptr) {
        cudaStreamCreateWithFlags(&s2, cudaStreamNonBlocking);
        cudaEventCreateWithFlags(&evFork, cudaEventDisableTiming);
        cudaEventCreateWithFlags(&evJoin, cudaEventDisableTiming);
    }

    // Fork: CSR build on s2, GEMM1+scores on main stream (independent work).
    cudaEventRecord(evFork, 0);
    cudaStreamWaitEvent(s2, evFork, 0);

    zero_counts_kernel<<<(M + 255) / 256, 256, 0, s2>>>(M);
    hist_kernel<<<(E + 255) / 256, 256, 0, s2>>>(dst, E);
    scan_sums_kernel<<<NB, SCAN_B, 0, s2>>>(M);
    scan_offsets_kernel<<<1, SCAN_B, 0, s2>>>(NB, M);
    scan_apply_kernel<<<NB, SCAN_B, 0, s2>>>(M);
    scatter_kernel<<<(E + 255) / 256, 256, 0, s2>>>(src, dst, E);
    cudaEventRecord(evJoin, s2);

    {
        dim3 grid(D1 / 64, (M + 63) / 64);
        gemm1_tf32_kernel<<<grid, 256>>>(x, W1, M);
    }
    scores1_kernel<<<(M * 32 + 255) / 256, 256>>>(asrc1, adst1, M);

    // Join: aggregate1 needs both CSR and h1/scores.
    cudaStreamWaitEvent(0, evJoin, 0);

    aggregate1_kernel<<<(M * 64 + 255) / 256, 256>>>(b1, M);

    // Layer 2
    gemm2_kernel<<<(M + 127) / 128, 256>>>(W2, asrc2, adst2, M);
    aggregate2_kernel<<<(M * 32 + 255) / 256, 256>>>(b2, out, M);
}

// round 11
// speedup vs baseline: 1.9926x; 1.5592x over previous
#include <cuda_runtime.h>
#include <cuda_bf16.h>
#include <float.h>

#define NNODES 100000
#define F_IN   128
#define D1     256      // 8 heads * 32
#define HEADS  8
#define NCLS   40
#define NEG    0.2f
#define EMAX   1600000
#define SCAN_B 1024

// ---------------- scratch (device globals; no allocation allowed) ----------
__device__ __align__(16) float g_h1[NNODES * D1];              // x @ W1 (fp32)
__device__ __align__(16) __nv_bfloat16 g_h1b[NNODES * D1];     // bf16 copy for gather
__device__ __align__(16) float g_h2[NNODES * D1];              // layer-1 output
__device__ float g_ssrc1[NNODES * HEADS];
__device__ float g_sdst1[NNODES * HEADS];
__device__ float g_pself1[NNODES * HEADS];
__device__ __align__(16) float g_h3[NNODES * NCLS];            // h2 @ W2
__device__ float g_ssrc2[NNODES];
__device__ float g_sdst2[NNODES];
__device__ float g_pself2[NNODES];
// CSR (dst-binned edges)
__device__ int g_counts[NNODES];
__device__ int g_rowptr[NNODES + 1];
__device__ int g_cursor[NNODES];
__device__ int g_csr_src[EMAX];
__device__ int g_bsum[(NNODES + SCAN_B - 1) / SCAN_B];
__device__ int g_boff[(NNODES + SCAN_B - 1) / SCAN_B];

__device__ __forceinline__ float lrelu(float v) { return v >= 0.f ? v : NEG * v; }
__device__ __forceinline__ unsigned f2tf32(float f) {
    unsigned u;
    asm("cvt.rna.tf32.f32 %0, %1;" : "=r"(u) : "f"(f));
    return u;
}

// ======================= CSR build ==========================================
__global__ __launch_bounds__(256) void zero_counts_kernel(int n) {
    int i = blockIdx.x * blockDim.x + threadIdx.x;
    if (i < n) g_counts[i] = 0;
}

__global__ __launch_bounds__(256) void hist_kernel(const int* __restrict__ dst, int E) {
    int e = blockIdx.x * blockDim.x + threadIdx.x;
    if (e < E) atomicAdd(&g_counts[dst[e]], 1);
}

__global__ __launch_bounds__(SCAN_B) void scan_sums_kernel(int n) {
    __shared__ int ws[32];
    int i = blockIdx.x * SCAN_B + threadIdx.x;
    int v = (i < n) ? g_counts[i] : 0;
    int lane = threadIdx.x & 31, w = threadIdx.x >> 5;
    int s = v;
#pragma unroll
    for (int o = 16; o; o >>= 1) s += __shfl_xor_sync(0xffffffffu, s, o);
    if (lane == 0) ws[w] = s;
    __syncthreads();
    if (w == 0) {
        int t = ws[lane];
#pragma unroll
        for (int o = 16; o; o >>= 1) t += __shfl_xor_sync(0xffffffffu, t, o);
        if (lane == 0) g_bsum[blockIdx.x] = t;
    }
}

__global__ __launch_bounds__(SCAN_B) void scan_offsets_kernel(int nb, int n) {
    __shared__ int ws[32];
    int lane = threadIdx.x & 31, w = threadIdx.x >> 5;
    int v = (threadIdx.x < nb) ? g_bsum[threadIdx.x] : 0;
    int x = v;
#pragma unroll
    for (int o = 1; o < 32; o <<= 1) {
        int y = __shfl_up_sync(0xffffffffu, x, o);
        if (lane >= o) x += y;
    }
    if (lane == 31) ws[w] = x;
    __syncthreads();
    if (w == 0) {
        int s = ws[lane];
#pragma unroll
        for (int o = 1; o < 32; o <<= 1) {
            int y = __shfl_up_sync(0xffffffffu, s, o);
            if (lane >= o) s += y;
        }
        ws[lane] = s;
    }
    __syncthreads();
    int incl = x + (w > 0 ? ws[w - 1] : 0);
    if (threadIdx.x < nb) g_boff[threadIdx.x] = incl - v;
    if (threadIdx.x == nb - 1) g_rowptr[n] = incl;
}

__global__ __launch_bounds__(SCAN_B) void scan_apply_kernel(int n) {
    __shared__ int ws[32];
    int i = blockIdx.x * SCAN_B + threadIdx.x;
    int v = (i < n) ? g_counts[i] : 0;
    int lane = threadIdx.x & 31, w = threadIdx.x >> 5;
    int x = v;
#pragma unroll
    for (int o = 1; o < 32; o <<= 1) {
        int y = __shfl_up_sync(0xffffffffu, x, o);
        if (lane >= o) x += y;
    }
    if (lane == 31) ws[w] = x;
    __syncthreads();
    if (w == 0) {
        int s = ws[lane];
#pragma unroll
        for (int o = 1; o < 32; o <<= 1) {
            int y = __shfl_up_sync(0xffffffffu, s, o);
            if (lane >= o) s += y;
        }
        ws[lane] = s;
    }
    __syncthreads();
    int excl = x - v + (w > 0 ? ws[w - 1] : 0) + g_boff[blockIdx.x];
    if (i < n) { g_rowptr[i] = excl; g_cursor[i] = excl; }
}

__global__ __launch_bounds__(256) void scatter_kernel(const int* __restrict__ src,
                                                      const int* __restrict__ dst, int E) {
    int e = blockIdx.x * blockDim.x + threadIdx.x;
    if (e >= E) return;
    int pos = atomicAdd(&g_cursor[dst[e]], 1);
    g_csr_src[pos] = src[e];
}

// ======== GEMM1 via tf32 mma.sync: h1[M,256] = x[M,128] @ W1[128,256] =======
__global__ __launch_bounds__(256) void gemm1_tf32_kernel(const float* __restrict__ A,
                                                         const float* __restrict__ B,
                                                         int M) {
    __shared__ unsigned As[64][36];
    __shared__ unsigned Bs[128][72];
    int tid = threadIdx.x;
    int warp = tid >> 5, lane = tid & 31;
    int q = lane >> 2, r4 = lane & 3;
    int rowBase = blockIdx.y * 64;
    int colBase = blockIdx.x * 64;
    int wm = (warp >> 2) * 32;
    int wn = (warp & 3) * 16;

    for (int j = tid; j < 2048; j += 256) {
        int k = j >> 4;
        int n4 = (j & 15) * 4;
        float4 v = *(const float4*)&B[(size_t)k * D1 + colBase + n4];
        uint4 t;
        t.x = f2tf32(v.x); t.y = f2tf32(v.y); t.z = f2tf32(v.z); t.w = f2tf32(v.w);
        *(uint4*)&Bs[k][n4] = t;
    }

    float c[2][2][4] = {};
    for (int kc = 0; kc < 4; kc++) {
        for (int j = tid; j < 512; j += 256) {
            int r = j >> 3;
            int k4 = (j & 7) * 4;
            int gr = rowBase + r;
            float4 v = make_float4(0.f, 0.f, 0.f, 0.f);
            if (gr < M) v = *(const float4*)&A[(size_t)gr * F_IN + kc * 32 + k4];
            uint4 t;
            t.x = f2tf32(v.x); t.y = f2tf32(v.y); t.z = f2tf32(v.z); t.w = f2tf32(v.w);
            *(uint4*)&As[r][k4] = t;
        }
        __syncthreads();
#pragma unroll
        for (int ks = 0; ks < 4; ks++) {
            int kk = ks * 8;
            unsigned a[2][4], b[2][2];
#pragma unroll
            for (int mt = 0; mt < 2; mt++) {
                int rr = wm + mt * 16 + q;
                a[mt][0] = As[rr][kk + r4];
                a[mt][1] = As[rr + 8][kk + r4];
                a[mt][2] = As[rr][kk + r4 + 4];
                a[mt][3] = As[rr + 8][kk + r4 + 4];
            }
#pragma unroll
            for (int nt = 0; nt < 2; nt++) {
                int cc = wn + nt * 8 + q;
                b[nt][0] = Bs[kc * 32 + kk + r4][cc];
                b[nt][1] = Bs[kc * 32 + kk + r4 + 4][cc];
            }
#pragma unroll
            for (int mt = 0; mt < 2; mt++)
#pragma unroll
                for (int nt = 0; nt < 2; nt++) {
                    asm volatile(
                        "mma.sync.aligned.m16n8k8.row.col.f32.tf32.tf32.f32 "
                        "{%0,%1,%2,%3}, {%4,%5,%6,%7}, {%8,%9}, {%0,%1,%2,%3};"
                        : "+f"(c[mt][nt][0]), "+f"(c[mt][nt][1]),
                          "+f"(c[mt][nt][2]), "+f"(c[mt][nt][3])
                        : "r"(a[mt][0]), "r"(a[mt][1]), "r"(a[mt][2]), "r"(a[mt][3]),
                          "r"(b[nt][0]), "r"(b[nt][1]));
                }
        }
        __syncthreads();
    }
#pragma unroll
    for (int mt = 0; mt < 2; mt++) {
        int r0 = rowBase + wm + mt * 16 + q;
#pragma unroll
        for (int nt = 0; nt < 2; nt++) {
            int col = colBase + wn + nt * 8 + r4 * 2;
            if (r0 < M) {
                float2 w0 = make_float2(c[mt][nt][0], c[mt][nt][1]);
                *(float2*)&g_h1[(size_t)r0 * D1 + col] = w0;
            }
            if (r0 + 8 < M) {
                float2 w1 = make_float2(c[mt][nt][2], c[mt][nt][3]);
                *(float2*)&g_h1[(size_t)(r0 + 8) * D1 + col] = w1;
            }
        }
    }
}

// ======== scores1 + bf16 copy: one pass over h1 =============================
__global__ __launch_bounds__(256) void scores1_kernel(const float* __restrict__ asrc,
                                                      const float* __restrict__ adst,
                                                      int n) {
    int wid  = (blockIdx.x * blockDim.x + threadIdx.x) >> 5;
    int lane = threadIdx.x & 31;
    if (wid >= n) return;
    size_t base = (size_t)wid * D1 + lane * 8;
    float4 v0 = *(const float4*)&g_h1[base];
    float4 v1 = *(const float4*)&g_h1[base + 4];
    float4 a0 = *(const float4*)&asrc[lane * 8];
    float4 a1 = *(const float4*)&asrc[lane * 8 + 4];
    float4 d0 = *(const float4*)&adst[lane * 8];
    float4 d1 = *(const float4*)&adst[lane * 8 + 4];
    float ps = v0.x*a0.x + v0.y*a0.y + v0.z*a0.z + v0.w*a0.w
             + v1.x*a1.x + v1.y*a1.y + v1.z*a1.z + v1.w*a1.w;
    float pd = v0.x*d0.x + v0.y*d0.y + v0.z*d0.z + v0.w*d0.w
             + v1.x*d1.x + v1.y*d1.y + v1.z*d1.z + v1.w*d1.w;
    ps += __shfl_xor_sync(0xffffffffu, ps, 1);
    ps += __shfl_xor_sync(0xffffffffu, ps, 2);
    pd += __shfl_xor_sync(0xffffffffu, pd, 1);
    pd += __shfl_xor_sync(0xffffffffu, pd, 2);
    int h = lane >> 2;
    if ((lane & 3) == 0) {
        g_ssrc1[wid * HEADS + h] = ps;
        g_sdst1[wid * HEADS + h] = pd;
        g_pself1[wid * HEADS + h] = __expf(lrelu(ps + pd));
    }
    __nv_bfloat162 p0 = __floats2bfloat162_rn(v0.x, v0.y);
    __nv_bfloat162 p1 = __floats2bfloat162_rn(v0.z, v0.w);
    __nv_bfloat162 p2 = __floats2bfloat162_rn(v1.x, v1.y);
    __nv_bfloat162 p3 = __floats2bfloat162_rn(v1.z, v1.w);
    uint4 pk;
    pk.x = *reinterpret_cast<unsigned*>(&p0);
    pk.y = *reinterpret_cast<unsigned*>(&p1);
    pk.z = *reinterpret_cast<unsigned*>(&p2);
    pk.w = *reinterpret_cast<unsigned*>(&p3);
    *(uint4*)&g_h1b[base] = pk;
}

// ======== aggregate1: 2 warps/node, bf16 gather, fp32 accumulate ============
__global__ __launch_bounds__(256) void aggregate1_kernel(const float* __restrict__ b1, int M) {
    int gw   = (blockIdx.x * blockDim.x + threadIdx.x) >> 5;
    int node = gw >> 1;
    int half = gw & 1;
    int lane = threadIdx.x & 31;
    if (node >= M) return;
    int ch = half * 128 + lane * 4;
    int h  = ch >> 5;
    float sdst_h = g_sdst1[node * HEADS + h];
    float pself  = g_pself1[node * HEADS + h];
    size_t nb = (size_t)node * D1 + ch;
    float4 a = *(const float4*)&g_h1[nb];
    float c0 = a.x * pself, c1 = a.y * pself, c2 = a.z * pself, c3 = a.w * pself;
    float denom = pself;
    int beg = g_rowptr[node], end = g_rowptr[node + 1];
    int i = beg;
    for (; i + 2 <= end; i += 2) {
        int s0 = __ldg(&g_csr_src[i]);
        int s1 = __ldg(&g_csr_src[i + 1]);
        float p0 = __expf(lrelu(__ldg(&g_ssrc1[s0 * HEADS + h]) + sdst_h));
        float p1 = __expf(lrelu(__ldg(&g_ssrc1[s1 * HEADS + h]) + sdst_h));
        uint2 r0 = *(const uint2*)&g_h1b[(size_t)s0 * D1 + ch];
        uint2 r1 = *(const uint2*)&g_h1b[(size_t)s1 * D1 + ch];
        float2 v0a = __bfloat1622float2(*reinterpret_cast<__nv_bfloat162*>(&r0.x));
        float2 v0b = __bfloat1622float2(*reinterpret_cast<__nv_bfloat162*>(&r0.y));
        float2 v1a = __bfloat1622float2(*reinterpret_cast<__nv_bfloat162*>(&r1.x));
        float2 v1b = __bfloat1622float2(*reinterpret_cast<__nv_bfloat162*>(&r1.y));
        c0 += v0a.x * p0 + v1a.x * p1;
        c1 += v0a.y * p0 + v1a.y * p1;
        c2 += v0b.x * p0 + v1b.x * p1;
        c3 += v0b.y * p0 + v1b.y * p1;
        denom += p0 + p1;
    }
    if (i < end) {
        int s = __ldg(&g_csr_src[i]);
        float p = __expf(lrelu(__ldg(&g_ssrc1[s * HEADS + h]) + sdst_h));
        uint2 r = *(const uint2*)&g_h1b[(size_t)s * D1 + ch];
        float2 va = __bfloat1622float2(*reinterpret_cast<__nv_bfloat162*>(&r.x));
        float2 vb = __bfloat1622float2(*reinterpret_cast<__nv_bfloat162*>(&r.y));
        c0 += va.x * p; c1 += va.y * p; c2 += vb.x * p; c3 += vb.y * p;
        denom += p;
    }
    float inv = __frcp_rn(denom);
    float4 bb = *(const float4*)&b1[ch];
    float4 o;
    o.x = fmaxf(c0 * inv + bb.x, 0.f);
    o.y = fmaxf(c1 * inv + bb.y, 0.f);
    o.z = fmaxf(c2 * inv + bb.z, 0.f);
    o.w = fmaxf(c3 * inv + bb.w, 0.f);
    *(float4*)&g_h2[nb] = o;
}

// ======== GEMM2 via tf32 mma.sync: h3[M,40] = h2[M,256] @ W2[256,40] ========
// Block 128 rows x 40 cols, 8 warps (each 16 rows x 5 n8 tiles), K chunks of 32.
__global__ __launch_bounds__(256) void gemm2_tf32_kernel(const float* __restrict__ B, int M) {
    __shared__ unsigned As[128][36];  // 128 rows x 32 k + pad4 (18.4 KB)
    __shared__ unsigned Bs[32][44];   // 32 k x 40 n + pad4      (5.6 KB)
    int tid = threadIdx.x;
    int warp = tid >> 5, lane = tid & 31;
    int q = lane >> 2, r4 = lane & 3;
    int rowBase = blockIdx.x * 128;
    int wm = warp * 16;

    float c[5][4] = {};
    for (int kc = 0; kc < 8; kc++) {
        // A chunk: 128 rows x 32 k
        for (int j = tid; j < 1024; j += 256) {
            int r = j >> 3;
            int k4 = (j & 7) * 4;
            int gr = rowBase + r;
            float4 v = make_float4(0.f, 0.f, 0.f, 0.f);
            if (gr < M) v = *(const float4*)&g_h2[(size_t)gr * D1 + kc * 32 + k4];
            uint4 t;
            t.x = f2tf32(v.x); t.y = f2tf32(v.y); t.z = f2tf32(v.z); t.w = f2tf32(v.w);
            *(uint4*)&As[r][k4] = t;
        }
        // B chunk: 32 k x 40 n
        for (int j = tid; j < 1280; j += 256) {
            int k = j / NCLS;
            int n = j - k * NCLS;
            Bs[k][n] = f2tf32(B[(size_t)(kc * 32 + k) * NCLS + n]);
        }
        __syncthreads();
#pragma unroll
        for (int ks = 0; ks < 4; ks++) {
            int kk = ks * 8;
            unsigned a[4];
            int rr = wm + q;
            a[0] = As[rr][kk + r4];
            a[1] = As[rr + 8][kk + r4];
            a[2] = As[rr][kk + r4 + 4];
            a[3] = As[rr + 8][kk + r4 + 4];
#pragma unroll
            for (int nt = 0; nt < 5; nt++) {
                unsigned b0 = Bs[kk + r4][nt * 8 + q];
                unsigned b1 = Bs[kk + r4 + 4][nt * 8 + q];
                asm volatile(
                    "mma.sync.aligned.m16n8k8.row.col.f32.tf32.tf32.f32 "
                    "{%0,%1,%2,%3}, {%4,%5,%6,%7}, {%8,%9}, {%0,%1,%2,%3};"
                    : "+f"(c[nt][0]), "+f"(c[nt][1]), "+f"(c[nt][2]), "+f"(c[nt][3])
                    : "r"(a[0]), "r"(a[1]), "r"(a[2]), "r"(a[3]),
                      "r"(b0), "r"(b1));
            }
        }
        __syncthreads();
    }
    int r0 = rowBase + wm + q;
#pragma unroll
    for (int nt = 0; nt < 5; nt++) {
        int col = nt * 8 + r4 * 2;
        if (r0 < M) {
            float2 w0 = make_float2(c[nt][0], c[nt][1]);
            *(float2*)&g_h3[(size_t)r0 * NCLS + col] = w0;
        }
        if (r0 + 8 < M) {
            float2 w1 = make_float2(c[nt][2], c[nt][3]);
            *(float2*)&g_h3[(size_t)(r0 + 8) * NCLS + col] = w1;
        }
    }
}

// ======== scores2: warp per node over h3 ====================================
__global__ __launch_bounds__(256) void scores2_kernel(const float* __restrict__ asrc,
                                                      const float* __restrict__ adst,
                                                      int n) {
    int wid  = (blockIdx.x * blockDim.x + threadIdx.x) >> 5;
    int lane = threadIdx.x & 31;
    if (wid >= n) return;
    size_t base = (size_t)wid * NCLS;
    float v0 = g_h3[base + lane];
    float v1 = (lane < 8) ? g_h3[base + 32 + lane] : 0.f;
    float a0 = asrc[lane], d0 = adst[lane];
    float a1 = (lane < 8) ? asrc[32 + lane] : 0.f;
    float d1 = (lane < 8) ? adst[32 + lane] : 0.f;
    float ps = v0 * a0 + v1 * a1;
    float pd = v0 * d0 + v1 * d1;
#pragma unroll
    for (int o = 16; o; o >>= 1) {
        ps += __shfl_xor_sync(0xffffffffu, ps, o);
        pd += __shfl_xor_sync(0xffffffffu, pd, o);
    }
    if (lane == 0) {
        g_ssrc2[wid] = ps;
        g_sdst2[wid] = pd;
        g_pself2[wid] = __expf(lrelu(ps + pd));
    }
}

// ======== aggregate2: node-per-warp, CSR, unroll-2, fused log_softmax ======
__global__ __launch_bounds__(256) void aggregate2_kernel(const float* __restrict__ b2,
                                                         float* __restrict__ out, int M) {
    int wid  = (blockIdx.x * blockDim.x + threadIdx.x) >> 5;
    int lane = threadIdx.x & 31;
    if (wid >= M) return;
    float sdst = g_sdst2[wid];
    float pself = g_pself2[wid];
    size_t nb = (size_t)wid * NCLS;
    float v0 = g_h3[nb + lane] * pself;
    float v1 = (lane < 8) ? g_h3[nb + 32 + lane] * pself : 0.f;
    float denom = pself;
    int beg = g_rowptr[wid], end = g_rowptr[wid + 1];
    int i = beg;
    for (; i + 2 <= end; i += 2) {
        int s0 = __ldg(&g_csr_src[i]);
        int s1 = __ldg(&g_csr_src[i + 1]);
        float p0 = __expf(lrelu(__ldg(&g_ssrc2[s0]) + sdst));
        float p1 = __expf(lrelu(__ldg(&g_ssrc2[s1]) + sdst));
        size_t sb0 = (size_t)s0 * NCLS, sb1 = (size_t)s1 * NCLS;
        v0 += p0 * g_h3[sb0 + lane] + p1 * g_h3[sb1 + lane];
        if (lane < 8) v1 += p0 * g_h3[sb0 + 32 + lane] + p1 * g_h3[sb1 + 32 + lane];
        denom += p0 + p1;
    }
    if (i < end) {
        int s = __ldg(&g_csr_src[i]);
        float p = __expf(lrelu(__ldg(&g_ssrc2[s]) + sdst));
        size_t sb = (size_t)s * NCLS;
        v0 += p * g_h3[sb + lane];
        if (lane < 8) v1 += p * g_h3[sb + 32 + lane];
        denom += p;
    }
    float inv = __frcp_rn(denom);
    float z0 = v0 * inv + b2[lane];
    float z1 = (lane < 8) ? (v1 * inv + b2[32 + lane]) : -FLT_MAX;
    float m = fmaxf(z0, z1);
#pragma unroll
    for (int o = 16; o; o >>= 1) m = fmaxf(m, __shfl_xor_sync(0xffffffffu, m, o));
    float s = expf(z0 - m) + ((lane < 8) ? expf(z1 - m) : 0.f);
#pragma unroll
    for (int o = 16; o; o >>= 1) s += __shfl_xor_sync(0xffffffffu, s, o);
    float ls = logf(s);
    out[nb + lane] = z0 - m - ls;
    if (lane < 8) out[nb + 32 + lane] = z1 - m - ls;
}

// ---------------------------------------------------------------------------
extern "C" void kernel_launch(void* const* d_in, const int* in_sizes, int n_in,
                              void* d_out, int out_size) {
    const float* x     = (const float*)d_in[0];
    const int*   ei    = (const int*)d_in[1];      // JAX x64 disabled -> int32
    const float* W1    = (const float*)d_in[2];
    const float* asrc1 = (const float*)d_in[3];
    const float* adst1 = (const float*)d_in[4];
    const float* b1    = (const float*)d_in[5];
    const float* W2    = (const float*)d_in[6];
    const float* asrc2 = (const float*)d_in[7];
    const float* adst2 = (const float*)d_in[8];
    const float* b2    = (const float*)d_in[9];
    float* out = (float*)d_out;

    int M = in_sizes[0] / F_IN;        // 100000
    int E = in_sizes[1] / 2;           // 1600000
    const int* src = ei;
    const int* dst = ei + E;
    int NB = (M + SCAN_B - 1) / SCAN_B;

    static cudaStream_t s2 = nullptr;
    static cudaEvent_t evFork = nullptr, evJoin = nullptr;
    if (s2 == nullptr) {
        cudaStreamCreateWithFlags(&s2, cudaStreamNonBlocking);
        cudaEventCreateWithFlags(&evFork, cudaEventDisableTiming);
        cudaEventCreateWithFlags(&evJoin, cudaEventDisableTiming);
    }

    // Fork: CSR build on s2, GEMM1+scores on main stream.
    cudaEventRecord(evFork, 0);
    cudaStreamWaitEvent(s2, evFork, 0);

    zero_counts_kernel<<<(M + 255) / 256, 256, 0, s2>>>(M);
    hist_kernel<<<(E + 255) / 256, 256, 0, s2>>>(dst, E);
    scan_sums_kernel<<<NB, SCAN_B, 0, s2>>>(M);
    scan_offsets_kernel<<<1, SCAN_B, 0, s2>>>(NB, M);
    scan_apply_kernel<<<NB, SCAN_B, 0, s2>>>(M);
    scatter_kernel<<<(E + 255) / 256, 256, 0, s2>>>(src, dst, E);
    cudaEventRecord(evJoin, s2);

    {
        dim3 grid(D1 / 64, (M + 63) / 64);
        gemm1_tf32_kernel<<<grid, 256>>>(x, W1, M);
    }
    scores1_kernel<<<(M * 32 + 255) / 256, 256>>>(asrc1, adst1, M);

    cudaStreamWaitEvent(0, evJoin, 0);

    aggregate1_kernel<<<(M * 64 + 255) / 256, 256>>>(b1, M);

    // Layer 2
    gemm2_tf32_kernel<<<(M + 127) / 128, 256>>>(W2, M);
    scores2_kernel<<<(M * 32 + 255) / 256, 256>>>(asrc2, adst2, M);
    aggregate2_kernel<<<(M * 32 + 255) / 256, 256>>>(b2, out, M);
}

// round 12
// speedup vs baseline: 2.1509x; 1.0794x over previous
#include <cuda_runtime.h>
#include <cuda_bf16.h>
#include <float.h>

#define NNODES 100000
#define F_IN   128
#define D1     256      // 8 heads * 32
#define HEADS  8
#define NCLS   40
#define NEG    0.2f
#define EMAX   1600000
#define SCAN_B 1024

// ---------------- scratch (device globals; no allocation allowed) ----------
__device__ __align__(16) float g_h1[NNODES * D1];              // x @ W1 (fp32)
__device__ __align__(16) __nv_bfloat16 g_h1b[NNODES * D1];     // bf16 copy for gather
__device__ __align__(16) float g_h2[NNODES * D1];              // layer-1 output
__device__ float g_ssrc1[NNODES * HEADS];
__device__ float g_sdst1[NNODES * HEADS];
__device__ float g_pself1[NNODES * HEADS];
__device__ __align__(16) float g_h3[NNODES * NCLS];            // h2 @ W2
__device__ float g_ssrc2[NNODES];
__device__ float g_sdst2[NNODES];
__device__ float g_pself2[NNODES];
// CSR (dst-binned edges)
__device__ int g_counts[NNODES];
__device__ int g_rowptr[NNODES + 1];
__device__ int g_cursor[NNODES];
__device__ int g_csr_src[EMAX];
__device__ int g_bsum[(NNODES + SCAN_B - 1) / SCAN_B];
__device__ int g_boff[(NNODES + SCAN_B - 1) / SCAN_B];

__device__ __forceinline__ float lrelu(float v) { return v >= 0.f ? v : NEG * v; }
__device__ __forceinline__ unsigned f2tf32(float f) {
    unsigned u;
    asm("cvt.rna.tf32.f32 %0, %1;" : "=r"(u) : "f"(f));
    return u;
}

// ======================= CSR build ==========================================
__global__ __launch_bounds__(256) void zero_counts_kernel(int n) {
    int i = blockIdx.x * blockDim.x + threadIdx.x;
    if (i < n) g_counts[i] = 0;
}

__global__ __launch_bounds__(256) void hist_kernel(const int* __restrict__ dst, int E) {
    int e = blockIdx.x * blockDim.x + threadIdx.x;
    if (e < E) atomicAdd(&g_counts[dst[e]], 1);
}

__global__ __launch_bounds__(SCAN_B) void scan_sums_kernel(int n) {
    __shared__ int ws[32];
    int i = blockIdx.x * SCAN_B + threadIdx.x;
    int v = (i < n) ? g_counts[i] : 0;
    int lane = threadIdx.x & 31, w = threadIdx.x >> 5;
    int s = v;
#pragma unroll
    for (int o = 16; o; o >>= 1) s += __shfl_xor_sync(0xffffffffu, s, o);
    if (lane == 0) ws[w] = s;
    __syncthreads();
    if (w == 0) {
        int t = ws[lane];
#pragma unroll
        for (int o = 16; o; o >>= 1) t += __shfl_xor_sync(0xffffffffu, t, o);
        if (lane == 0) g_bsum[blockIdx.x] = t;
    }
}

__global__ __launch_bounds__(SCAN_B) void scan_offsets_kernel(int nb, int n) {
    __shared__ int ws[32];
    int lane = threadIdx.x & 31, w = threadIdx.x >> 5;
    int v = (threadIdx.x < nb) ? g_bsum[threadIdx.x] : 0;
    int x = v;
#pragma unroll
    for (int o = 1; o < 32; o <<= 1) {
        int y = __shfl_up_sync(0xffffffffu, x, o);
        if (lane >= o) x += y;
    }
    if (lane == 31) ws[w] = x;
    __syncthreads();
    if (w == 0) {
        int s = ws[lane];
#pragma unroll
        for (int o = 1; o < 32; o <<= 1) {
            int y = __shfl_up_sync(0xffffffffu, s, o);
            if (lane >= o) s += y;
        }
        ws[lane] = s;
    }
    __syncthreads();
    int incl = x + (w > 0 ? ws[w - 1] : 0);
    if (threadIdx.x < nb) g_boff[threadIdx.x] = incl - v;
    if (threadIdx.x == nb - 1) g_rowptr[n] = incl;
}

__global__ __launch_bounds__(SCAN_B) void scan_apply_kernel(int n) {
    __shared__ int ws[32];
    int i = blockIdx.x * SCAN_B + threadIdx.x;
    int v = (i < n) ? g_counts[i] : 0;
    int lane = threadIdx.x & 31, w = threadIdx.x >> 5;
    int x = v;
#pragma unroll
    for (int o = 1; o < 32; o <<= 1) {
        int y = __shfl_up_sync(0xffffffffu, x, o);
        if (lane >= o) x += y;
    }
    if (lane == 31) ws[w] = x;
    __syncthreads();
    if (w == 0) {
        int s = ws[lane];
#pragma unroll
        for (int o = 1; o < 32; o <<= 1) {
            int y = __shfl_up_sync(0xffffffffu, s, o);
            if (lane >= o) s += y;
        }
        ws[lane] = s;
    }
    __syncthreads();
    int excl = x - v + (w > 0 ? ws[w - 1] : 0) + g_boff[blockIdx.x];
    if (i < n) { g_rowptr[i] = excl; g_cursor[i] = excl; }
}

__global__ __launch_bounds__(256) void scatter_kernel(const int* __restrict__ src,
                                                      const int* __restrict__ dst, int E) {
    int e = blockIdx.x * blockDim.x + threadIdx.x;
    if (e >= E) return;
    int pos = atomicAdd(&g_cursor[dst[e]], 1);
    g_csr_src[pos] = src[e];
}

// ======== GEMM1 via tf32 mma.sync: h1[M,256] = x[M,128] @ W1[128,256] =======
__global__ __launch_bounds__(256) void gemm1_tf32_kernel(const float* __restrict__ A,
                                                         const float* __restrict__ B,
                                                         int M) {
    __shared__ unsigned As[64][36];
    __shared__ unsigned Bs[128][72];
    int tid = threadIdx.x;
    int warp = tid >> 5, lane = tid & 31;
    int q = lane >> 2, r4 = lane & 3;
    int rowBase = blockIdx.y * 64;
    int colBase = blockIdx.x * 64;
    int wm = (warp >> 2) * 32;
    int wn = (warp & 3) * 16;

    for (int j = tid; j < 2048; j += 256) {
        int k = j >> 4;
        int n4 = (j & 15) * 4;
        float4 v = *(const float4*)&B[(size_t)k * D1 + colBase + n4];
        uint4 t;
        t.x = f2tf32(v.x); t.y = f2tf32(v.y); t.z = f2tf32(v.z); t.w = f2tf32(v.w);
        *(uint4*)&Bs[k][n4] = t;
    }

    float c[2][2][4] = {};
    for (int kc = 0; kc < 4; kc++) {
        for (int j = tid; j < 512; j += 256) {
            int r = j >> 3;
            int k4 = (j & 7) * 4;
            int gr = rowBase + r;
            float4 v = make_float4(0.f, 0.f, 0.f, 0.f);
            if (gr < M) v = *(const float4*)&A[(size_t)gr * F_IN + kc * 32 + k4];
            uint4 t;
            t.x = f2tf32(v.x); t.y = f2tf32(v.y); t.z = f2tf32(v.z); t.w = f2tf32(v.w);
            *(uint4*)&As[r][k4] = t;
        }
        __syncthreads();
#pragma unroll
        for (int ks = 0; ks < 4; ks++) {
            int kk = ks * 8;
            unsigned a[2][4], b[2][2];
#pragma unroll
            for (int mt = 0; mt < 2; mt++) {
                int rr = wm + mt * 16 + q;
                a[mt][0] = As[rr][kk + r4];
                a[mt][1] = As[rr + 8][kk + r4];
                a[mt][2] = As[rr][kk + r4 + 4];
                a[mt][3] = As[rr + 8][kk + r4 + 4];
            }
#pragma unroll
            for (int nt = 0; nt < 2; nt++) {
                int cc = wn + nt * 8 + q;
                b[nt][0] = Bs[kc * 32 + kk + r4][cc];
                b[nt][1] = Bs[kc * 32 + kk + r4 + 4][cc];
            }
#pragma unroll
            for (int mt = 0; mt < 2; mt++)
#pragma unroll
                for (int nt = 0; nt < 2; nt++) {
                    asm volatile(
                        "mma.sync.aligned.m16n8k8.row.col.f32.tf32.tf32.f32 "
                        "{%0,%1,%2,%3}, {%4,%5,%6,%7}, {%8,%9}, {%0,%1,%2,%3};"
                        : "+f"(c[mt][nt][0]), "+f"(c[mt][nt][1]),
                          "+f"(c[mt][nt][2]), "+f"(c[mt][nt][3])
                        : "r"(a[mt][0]), "r"(a[mt][1]), "r"(a[mt][2]), "r"(a[mt][3]),
                          "r"(b[nt][0]), "r"(b[nt][1]));
                }
        }
        __syncthreads();
    }
#pragma unroll
    for (int mt = 0; mt < 2; mt++) {
        int r0 = rowBase + wm + mt * 16 + q;
#pragma unroll
        for (int nt = 0; nt < 2; nt++) {
            int col = colBase + wn + nt * 8 + r4 * 2;
            if (r0 < M) {
                float2 w0 = make_float2(c[mt][nt][0], c[mt][nt][1]);
                *(float2*)&g_h1[(size_t)r0 * D1 + col] = w0;
            }
            if (r0 + 8 < M) {
                float2 w1 = make_float2(c[mt][nt][2], c[mt][nt][3]);
                *(float2*)&g_h1[(size_t)(r0 + 8) * D1 + col] = w1;
            }
        }
    }
}

// ======== scores1 + bf16 copy: one pass over h1 =============================
__global__ __launch_bounds__(256) void scores1_kernel(const float* __restrict__ asrc,
                                                      const float* __restrict__ adst,
                                                      int n) {
    int wid  = (blockIdx.x * blockDim.x + threadIdx.x) >> 5;
    int lane = threadIdx.x & 31;
    if (wid >= n) return;
    size_t base = (size_t)wid * D1 + lane * 8;
    float4 v0 = *(const float4*)&g_h1[base];
    float4 v1 = *(const float4*)&g_h1[base + 4];
    float4 a0 = *(const float4*)&asrc[lane * 8];
    float4 a1 = *(const float4*)&asrc[lane * 8 + 4];
    float4 d0 = *(const float4*)&adst[lane * 8];
    float4 d1 = *(const float4*)&adst[lane * 8 + 4];
    float ps = v0.x*a0.x + v0.y*a0.y + v0.z*a0.z + v0.w*a0.w
             + v1.x*a1.x + v1.y*a1.y + v1.z*a1.z + v1.w*a1.w;
    float pd = v0.x*d0.x + v0.y*d0.y + v0.z*d0.z + v0.w*d0.w
             + v1.x*d1.x + v1.y*d1.y + v1.z*d1.z + v1.w*d1.w;
    ps += __shfl_xor_sync(0xffffffffu, ps, 1);
    ps += __shfl_xor_sync(0xffffffffu, ps, 2);
    pd += __shfl_xor_sync(0xffffffffu, pd, 1);
    pd += __shfl_xor_sync(0xffffffffu, pd, 2);
    int h = lane >> 2;
    if ((lane & 3) == 0) {
        g_ssrc1[wid * HEADS + h] = ps;
        g_sdst1[wid * HEADS + h] = pd;
        g_pself1[wid * HEADS + h] = __expf(lrelu(ps + pd));
    }
    __nv_bfloat162 p0 = __floats2bfloat162_rn(v0.x, v0.y);
    __nv_bfloat162 p1 = __floats2bfloat162_rn(v0.z, v0.w);
    __nv_bfloat162 p2 = __floats2bfloat162_rn(v1.x, v1.y);
    __nv_bfloat162 p3 = __floats2bfloat162_rn(v1.z, v1.w);
    uint4 pk;
    pk.x = *reinterpret_cast<unsigned*>(&p0);
    pk.y = *reinterpret_cast<unsigned*>(&p1);
    pk.z = *reinterpret_cast<unsigned*>(&p2);
    pk.w = *reinterpret_cast<unsigned*>(&p3);
    *(uint4*)&g_h1b[base] = pk;
}

// ======== aggregate1: 1 warp/node, 8 ch/lane, uint4 bf16 gather, unroll-4 ===
__global__ __launch_bounds__(256) void aggregate1_kernel(const float* __restrict__ b1, int M) {
    int node = (blockIdx.x * blockDim.x + threadIdx.x) >> 5;
    int lane = threadIdx.x & 31;
    if (node >= M) return;
    int ch = lane * 8;                       // 8 channels per lane (uint4 of bf16)
    int h  = lane >> 2;                      // head = ch/32
    float sdst_h = g_sdst1[node * HEADS + h];
    float pself  = g_pself1[node * HEADS + h];
    size_t nb = (size_t)node * D1 + ch;
    float4 a0 = *(const float4*)&g_h1[nb];       // self term fp32
    float4 a1 = *(const float4*)&g_h1[nb + 4];
    float c0 = a0.x * pself, c1 = a0.y * pself, c2 = a0.z * pself, c3 = a0.w * pself;
    float c4 = a1.x * pself, c5 = a1.y * pself, c6 = a1.z * pself, c7 = a1.w * pself;
    float denom = pself;
    int beg = g_rowptr[node], end = g_rowptr[node + 1];
    int i = beg;
    for (; i + 4 <= end; i += 4) {
        int s0 = __ldg(&g_csr_src[i]);
        int s1 = __ldg(&g_csr_src[i + 1]);
        int s2 = __ldg(&g_csr_src[i + 2]);
        int s3 = __ldg(&g_csr_src[i + 3]);
        float e0 = __ldg(&g_ssrc1[s0 * HEADS + h]);
        float e1 = __ldg(&g_ssrc1[s1 * HEADS + h]);
        float e2 = __ldg(&g_ssrc1[s2 * HEADS + h]);
        float e3 = __ldg(&g_ssrc1[s3 * HEADS + h]);
        uint4 r0 = *(const uint4*)&g_h1b[(size_t)s0 * D1 + ch];
        uint4 r1 = *(const uint4*)&g_h1b[(size_t)s1 * D1 + ch];
        uint4 r2 = *(const uint4*)&g_h1b[(size_t)s2 * D1 + ch];
        uint4 r3 = *(const uint4*)&g_h1b[(size_t)s3 * D1 + ch];
        float p0 = __expf(lrelu(e0 + sdst_h));
        float p1 = __expf(lrelu(e1 + sdst_h));
        float p2 = __expf(lrelu(e2 + sdst_h));
        float p3 = __expf(lrelu(e3 + sdst_h));
        {
            float2 va = __bfloat1622float2(*reinterpret_cast<__nv_bfloat162*>(&r0.x));
            float2 vb = __bfloat1622float2(*reinterpret_cast<__nv_bfloat162*>(&r0.y));
            float2 vc = __bfloat1622float2(*reinterpret_cast<__nv_bfloat162*>(&r0.z));
            float2 vd = __bfloat1622float2(*reinterpret_cast<__nv_bfloat162*>(&r0.w));
            c0 += va.x * p0; c1 += va.y * p0; c2 += vb.x * p0; c3 += vb.y * p0;
            c4 += vc.x * p0; c5 += vc.y * p0; c6 += vd.x * p0; c7 += vd.y * p0;
        }
        {
            float2 va = __bfloat1622float2(*reinterpret_cast<__nv_bfloat162*>(&r1.x));
            float2 vb = __bfloat1622float2(*reinterpret_cast<__nv_bfloat162*>(&r1.y));
            float2 vc = __bfloat1622float2(*reinterpret_cast<__nv_bfloat162*>(&r1.z));
            float2 vd = __bfloat1622float2(*reinterpret_cast<__nv_bfloat162*>(&r1.w));
            c0 += va.x * p1; c1 += va.y * p1; c2 += vb.x * p1; c3 += vb.y * p1;
            c4 += vc.x * p1; c5 += vc.y * p1; c6 += vd.x * p1; c7 += vd.y * p1;
        }
        {
            float2 va = __bfloat1622float2(*reinterpret_cast<__nv_bfloat162*>(&r2.x));
            float2 vb = __bfloat1622float2(*reinterpret_cast<__nv_bfloat162*>(&r2.y));
            float2 vc = __bfloat1622float2(*reinterpret_cast<__nv_bfloat162*>(&r2.z));
            float2 vd = __bfloat1622float2(*reinterpret_cast<__nv_bfloat162*>(&r2.w));
            c0 += va.x * p2; c1 += va.y * p2; c2 += vb.x * p2; c3 += vb.y * p2;
            c4 += vc.x * p2; c5 += vc.y * p2; c6 += vd.x * p2; c7 += vd.y * p2;
        }
        {
            float2 va = __bfloat1622float2(*reinterpret_cast<__nv_bfloat162*>(&r3.x));
            float2 vb = __bfloat1622float2(*reinterpret_cast<__nv_bfloat162*>(&r3.y));
            float2 vc = __bfloat1622float2(*reinterpret_cast<__nv_bfloat162*>(&r3.z));
            float2 vd = __bfloat1622float2(*reinterpret_cast<__nv_bfloat162*>(&r3.w));
            c0 += va.x * p3; c1 += va.y * p3; c2 += vb.x * p3; c3 += vb.y * p3;
            c4 += vc.x * p3; c5 += vc.y * p3; c6 += vd.x * p3; c7 += vd.y * p3;
        }
        denom += (p0 + p1) + (p2 + p3);
    }
    for (; i < end; i++) {
        int s = __ldg(&g_csr_src[i]);
        float e = __ldg(&g_ssrc1[s * HEADS + h]);
        uint4 r = *(const uint4*)&g_h1b[(size_t)s * D1 + ch];
        float p = __expf(lrelu(e + sdst_h));
        float2 va = __bfloat1622float2(*reinterpret_cast<__nv_bfloat162*>(&r.x));
        float2 vb = __bfloat1622float2(*reinterpret_cast<__nv_bfloat162*>(&r.y));
        float2 vc = __bfloat1622float2(*reinterpret_cast<__nv_bfloat162*>(&r.z));
        float2 vd = __bfloat1622float2(*reinterpret_cast<__nv_bfloat162*>(&r.w));
        c0 += va.x * p; c1 += va.y * p; c2 += vb.x * p; c3 += vb.y * p;
        c4 += vc.x * p; c5 += vc.y * p; c6 += vd.x * p; c7 += vd.y * p;
        denom += p;
    }
    float inv = __frcp_rn(denom);
    float4 bb0 = *(const float4*)&b1[ch];
    float4 bb1 = *(const float4*)&b1[ch + 4];
    float4 o0, o1;
    o0.x = fmaxf(c0 * inv + bb0.x, 0.f); o0.y = fmaxf(c1 * inv + bb0.y, 0.f);
    o0.z = fmaxf(c2 * inv + bb0.z, 0.f); o0.w = fmaxf(c3 * inv + bb0.w, 0.f);
    o1.x = fmaxf(c4 * inv + bb1.x, 0.f); o1.y = fmaxf(c5 * inv + bb1.y, 0.f);
    o1.z = fmaxf(c6 * inv + bb1.z, 0.f); o1.w = fmaxf(c7 * inv + bb1.w, 0.f);
    *(float4*)&g_h2[nb]     = o0;
    *(float4*)&g_h2[nb + 4] = o1;
}

// ======== GEMM2 via tf32 mma.sync: h3[M,40] = h2[M,256] @ W2[256,40] ========
__global__ __launch_bounds__(256) void gemm2_tf32_kernel(const float* __restrict__ B, int M) {
    __shared__ unsigned As[128][36];
    __shared__ unsigned Bs[32][44];
    int tid = threadIdx.x;
    int warp = tid >> 5, lane = tid & 31;
    int q = lane >> 2, r4 = lane & 3;
    int rowBase = blockIdx.x * 128;
    int wm = warp * 16;

    float c[5][4] = {};
    for (int kc = 0; kc < 8; kc++) {
        for (int j = tid; j < 1024; j += 256) {
            int r = j >> 3;
            int k4 = (j & 7) * 4;
            int gr = rowBase + r;
            float4 v = make_float4(0.f, 0.f, 0.f, 0.f);
            if (gr < M) v = *(const float4*)&g_h2[(size_t)gr * D1 + kc * 32 + k4];
            uint4 t;
            t.x = f2tf32(v.x); t.y = f2tf32(v.y); t.z = f2tf32(v.z); t.w = f2tf32(v.w);
            *(uint4*)&As[r][k4] = t;
        }
        for (int j = tid; j < 1280; j += 256) {
            int k = j / NCLS;
            int n = j - k * NCLS;
            Bs[k][n] = f2tf32(B[(size_t)(kc * 32 + k) * NCLS + n]);
        }
        __syncthreads();
#pragma unroll
        for (int ks = 0; ks < 4; ks++) {
            int kk = ks * 8;
            unsigned a[4];
            int rr = wm + q;
            a[0] = As[rr][kk + r4];
            a[1] = As[rr + 8][kk + r4];
            a[2] = As[rr][kk + r4 + 4];
            a[3] = As[rr + 8][kk + r4 + 4];
#pragma unroll
            for (int nt = 0; nt < 5; nt++) {
                unsigned b0 = Bs[kk + r4][nt * 8 + q];
                unsigned b1 = Bs[kk + r4 + 4][nt * 8 + q];
                asm volatile(
                    "mma.sync.aligned.m16n8k8.row.col.f32.tf32.tf32.f32 "
                    "{%0,%1,%2,%3}, {%4,%5,%6,%7}, {%8,%9}, {%0,%1,%2,%3};"
                    : "+f"(c[nt][0]), "+f"(c[nt][1]), "+f"(c[nt][2]), "+f"(c[nt][3])
                    : "r"(a[0]), "r"(a[1]), "r"(a[2]), "r"(a[3]),
                      "r"(b0), "r"(b1));
            }
        }
        __syncthreads();
    }
    int r0 = rowBase + wm + q;
#pragma unroll
    for (int nt = 0; nt < 5; nt++) {
        int col = nt * 8 + r4 * 2;
        if (r0 < M) {
            float2 w0 = make_float2(c[nt][0], c[nt][1]);
            *(float2*)&g_h3[(size_t)r0 * NCLS + col] = w0;
        }
        if (r0 + 8 < M) {
            float2 w1 = make_float2(c[nt][2], c[nt][3]);
            *(float2*)&g_h3[(size_t)(r0 + 8) * NCLS + col] = w1;
        }
    }
}

// ======== scores2: warp per node over h3 ====================================
__global__ __launch_bounds__(256) void scores2_kernel(const float* __restrict__ asrc,
                                                      const float* __restrict__ adst,
                                                      int n) {
    int wid  = (blockIdx.x * blockDim.x + threadIdx.x) >> 5;
    int lane = threadIdx.x & 31;
    if (wid >= n) return;
    size_t base = (size_t)wid * NCLS;
    float v0 = g_h3[base + lane];
    float v1 = (lane < 8) ? g_h3[base + 32 + lane] : 0.f;
    float a0 = asrc[lane], d0 = adst[lane];
    float a1 = (lane < 8) ? asrc[32 + lane] : 0.f;
    float d1 = (lane < 8) ? adst[32 + lane] : 0.f;
    float ps = v0 * a0 + v1 * a1;
    float pd = v0 * d0 + v1 * d1;
#pragma unroll
    for (int o = 16; o; o >>= 1) {
        ps += __shfl_xor_sync(0xffffffffu, ps, o);
        pd += __shfl_xor_sync(0xffffffffu, pd, o);
    }
    if (lane == 0) {
        g_ssrc2[wid] = ps;
        g_sdst2[wid] = pd;
        g_pself2[wid] = __expf(lrelu(ps + pd));
    }
}

// ======== aggregate2: node-per-warp, CSR, unroll-2, fused log_softmax ======
__global__ __launch_bounds__(256) void aggregate2_kernel(const float* __restrict__ b2,
                                                         float* __restrict__ out, int M) {
    int wid  = (blockIdx.x * blockDim.x + threadIdx.x) >> 5;
    int lane = threadIdx.x & 31;
    if (wid >= M) return;
    float sdst = g_sdst2[wid];
    float pself = g_pself2[wid];
    size_t nb = (size_t)wid * NCLS;
    float v0 = g_h3[nb + lane] * pself;
    float v1 = (lane < 8) ? g_h3[nb + 32 + lane] * pself : 0.f;
    float denom = pself;
    int beg = g_rowptr[wid], end = g_rowptr[wid + 1];
    int i = beg;
    for (; i + 2 <= end; i += 2) {
        int s0 = __ldg(&g_csr_src[i]);
        int s1 = __ldg(&g_csr_src[i + 1]);
        float p0 = __expf(lrelu(__ldg(&g_ssrc2[s0]) + sdst));
        float p1 = __expf(lrelu(__ldg(&g_ssrc2[s1]) + sdst));
        size_t sb0 = (size_t)s0 * NCLS, sb1 = (size_t)s1 * NCLS;
        v0 += p0 * g_h3[sb0 + lane] + p1 * g_h3[sb1 + lane];
        if (lane < 8) v1 += p0 * g_h3[sb0 + 32 + lane] + p1 * g_h3[sb1 + 32 + lane];
        denom += p0 + p1;
    }
    if (i < end) {
        int s = __ldg(&g_csr_src[i]);
        float p = __expf(lrelu(__ldg(&g_ssrc2[s]) + sdst));
        size_t sb = (size_t)s * NCLS;
        v0 += p * g_h3[sb + lane];
        if (lane < 8) v1 += p * g_h3[sb + 32 + lane];
        denom += p;
    }
    float inv = __frcp_rn(denom);
    float z0 = v0 * inv + b2[lane];
    float z1 = (lane < 8) ? (v1 * inv + b2[32 + lane]) : -FLT_MAX;
    float m = fmaxf(z0, z1);
#pragma unroll
    for (int o = 16; o; o >>= 1) m = fmaxf(m, __shfl_xor_sync(0xffffffffu, m, o));
    float s = expf(z0 - m) + ((lane < 8) ? expf(z1 - m) : 0.f);
#pragma unroll
    for (int o = 16; o; o >>= 1) s += __shfl_xor_sync(0xffffffffu, s, o);
    float ls = logf(s);
    out[nb + lane] = z0 - m - ls;
    if (lane < 8) out[nb + 32 + lane] = z1 - m - ls;
}

// ---------------------------------------------------------------------------
extern "C" void kernel_launch(void* const* d_in, const int* in_sizes, int n_in,
                              void* d_out, int out_size) {
    const float* x     = (const float*)d_in[0];
    const int*   ei    = (const int*)d_in[1];      // JAX x64 disabled -> int32
    const float* W1    = (const float*)d_in[2];
    const float* asrc1 = (const float*)d_in[3];
    const float* adst1 = (const float*)d_in[4];
    const float* b1    = (const float*)d_in[5];
    const float* W2    = (const float*)d_in[6];
    const float* asrc2 = (const float*)d_in[7];
    const float* adst2 = (const float*)d_in[8];
    const float* b2    = (const float*)d_in[9];
    float* out = (float*)d_out;

    int M = in_sizes[0] / F_IN;        // 100000
    int E = in_sizes[1] / 2;           // 1600000
    const int* src = ei;
    const int* dst = ei + E;
    int NB = (M + SCAN_B - 1) / SCAN_B;

    static cudaStream_t s2 = nullptr;
    static cudaEvent_t evFork = nullptr, evJoin = nullptr;
    if (s2 == nullptr) {
        cudaStreamCreateWithFlags(&s2, cudaStreamNonBlocking);
        cudaEventCreateWithFlags(&evFork, cudaEventDisableTiming);
        cudaEventCreateWithFlags(&evJoin, cudaEventDisableTiming);
    }

    // Fork: CSR build on s2, GEMM1+scores on main stream.
    cudaEventRecord(evFork, 0);
    cudaStreamWaitEvent(s2, evFork, 0);

    zero_counts_kernel<<<(M + 255) / 256, 256, 0, s2>>>(M);
    hist_kernel<<<(E + 255) / 256, 256, 0, s2>>>(dst, E);
    scan_sums_kernel<<<NB, SCAN_B, 0, s2>>>(M);
    scan_offsets_kernel<<<1, SCAN_B, 0, s2>>>(NB, M);
    scan_apply_kernel<<<NB, SCAN_B, 0, s2>>>(M);
    scatter_kernel<<<(E + 255) / 256, 256, 0, s2>>>(src, dst, E);
    cudaEventRecord(evJoin, s2);

    {
        dim3 grid(D1 / 64, (M + 63) / 64);
        gemm1_tf32_kernel<<<grid, 256>>>(x, W1, M);
    }
    scores1_kernel<<<(M * 32 + 255) / 256, 256>>>(asrc1, adst1, M);

    cudaStreamWaitEvent(0, evJoin, 0);

    aggregate1_kernel<<<(M * 32 + 255) / 256, 256>>>(b1, M);

    // Layer 2
    gemm2_tf32_kernel<<<(M + 127) / 128, 256>>>(W2, M);
    scores2_kernel<<<(M * 32 + 255) / 256, 256>>>(asrc2, adst2, M);
    aggregate2_kernel<<<(M * 32 + 255) / 256, 256>>>(b2, out, M);
}

// round 13
// speedup vs baseline: 2.1682x; 1.0080x over previous
#include <cuda_runtime.h>
#include <cuda_bf16.h>
#include <float.h>

#define NNODES 100000
#define F_IN   128
#define D1     256      // 8 heads * 32
#define HEADS  8
#define NCLS   40
#define NEG    0.2f
#define EMAX   1600000
#define SCAN_B 1024

// ---------------- scratch (device globals; no allocation allowed) ----------
__device__ __align__(16) float g_h1[NNODES * D1];              // x @ W1 (fp32)
__device__ __align__(16) __nv_bfloat16 g_h1b[NNODES * D1];     // bf16 copy for gather
__device__ __align__(16) float g_h2[NNODES * D1];              // layer-1 output
__device__ float g_ssrc1[NNODES * HEADS];
__device__ float g_sdst1[NNODES * HEADS];
__device__ float g_pself1[NNODES * HEADS];
__device__ __align__(16) float g_h3[NNODES * NCLS];            // h2 @ W2 (fp32)
__device__ __align__(16) __nv_bfloat16 g_h3b[NNODES * NCLS];   // bf16 copy for gather
__device__ float g_ssrc2[NNODES];
__device__ float g_sdst2[NNODES];
__device__ float g_pself2[NNODES];
// CSR (dst-binned edges)
__device__ int g_counts[NNODES];
__device__ int g_rowptr[NNODES + 1];
__device__ int g_cursor[NNODES];
__device__ int g_csr_src[EMAX];
__device__ int g_bsum[(NNODES + SCAN_B - 1) / SCAN_B];
__device__ int g_boff[(NNODES + SCAN_B - 1) / SCAN_B];

__device__ __forceinline__ float lrelu(float v) { return v >= 0.f ? v : NEG * v; }
__device__ __forceinline__ unsigned f2tf32(float f) {
    unsigned u;
    asm("cvt.rna.tf32.f32 %0, %1;" : "=r"(u) : "f"(f));
    return u;
}

// ======================= CSR build ==========================================
__global__ __launch_bounds__(256) void zero_counts_kernel(int n) {
    int i = blockIdx.x * blockDim.x + threadIdx.x;
    if (i < n) g_counts[i] = 0;
}

__global__ __launch_bounds__(256) void hist_kernel(const int* __restrict__ dst, int E) {
    int e = blockIdx.x * blockDim.x + threadIdx.x;
    if (e < E) atomicAdd(&g_counts[dst[e]], 1);
}

__global__ __launch_bounds__(SCAN_B) void scan_sums_kernel(int n) {
    __shared__ int ws[32];
    int i = blockIdx.x * SCAN_B + threadIdx.x;
    int v = (i < n) ? g_counts[i] : 0;
    int lane = threadIdx.x & 31, w = threadIdx.x >> 5;
    int s = v;
#pragma unroll
    for (int o = 16; o; o >>= 1) s += __shfl_xor_sync(0xffffffffu, s, o);
    if (lane == 0) ws[w] = s;
    __syncthreads();
    if (w == 0) {
        int t = ws[lane];
#pragma unroll
        for (int o = 16; o; o >>= 1) t += __shfl_xor_sync(0xffffffffu, t, o);
        if (lane == 0) g_bsum[blockIdx.x] = t;
    }
}

__global__ __launch_bounds__(SCAN_B) void scan_offsets_kernel(int nb, int n) {
    __shared__ int ws[32];
    int lane = threadIdx.x & 31, w = threadIdx.x >> 5;
    int v = (threadIdx.x < nb) ? g_bsum[threadIdx.x] : 0;
    int x = v;
#pragma unroll
    for (int o = 1; o < 32; o <<= 1) {
        int y = __shfl_up_sync(0xffffffffu, x, o);
        if (lane >= o) x += y;
    }
    if (lane == 31) ws[w] = x;
    __syncthreads();
    if (w == 0) {
        int s = ws[lane];
#pragma unroll
        for (int o = 1; o < 32; o <<= 1) {
            int y = __shfl_up_sync(0xffffffffu, s, o);
            if (lane >= o) s += y;
        }
        ws[lane] = s;
    }
    __syncthreads();
    int incl = x + (w > 0 ? ws[w - 1] : 0);
    if (threadIdx.x < nb) g_boff[threadIdx.x] = incl - v;
    if (threadIdx.x == nb - 1) g_rowptr[n] = incl;
}

__global__ __launch_bounds__(SCAN_B) void scan_apply_kernel(int n) {
    __shared__ int ws[32];
    int i = blockIdx.x * SCAN_B + threadIdx.x;
    int v = (i < n) ? g_counts[i] : 0;
    int lane = threadIdx.x & 31, w = threadIdx.x >> 5;
    int x = v;
#pragma unroll
    for (int o = 1; o < 32; o <<= 1) {
        int y = __shfl_up_sync(0xffffffffu, x, o);
        if (lane >= o) x += y;
    }
    if (lane == 31) ws[w] = x;
    __syncthreads();
    if (w == 0) {
        int s = ws[lane];
#pragma unroll
        for (int o = 1; o < 32; o <<= 1) {
            int y = __shfl_up_sync(0xffffffffu, s, o);
            if (lane >= o) s += y;
        }
        ws[lane] = s;
    }
    __syncthreads();
    int excl = x - v + (w > 0 ? ws[w - 1] : 0) + g_boff[blockIdx.x];
    if (i < n) { g_rowptr[i] = excl; g_cursor[i] = excl; }
}

__global__ __launch_bounds__(256) void scatter_kernel(const int* __restrict__ src,
                                                      const int* __restrict__ dst, int E) {
    int e = blockIdx.x * blockDim.x + threadIdx.x;
    if (e >= E) return;
    int pos = atomicAdd(&g_cursor[dst[e]], 1);
    g_csr_src[pos] = src[e];
}

// ======== GEMM1 via tf32 mma.sync: h1[M,256] = x[M,128] @ W1[128,256] =======
__global__ __launch_bounds__(256) void gemm1_tf32_kernel(const float* __restrict__ A,
                                                         const float* __restrict__ B,
                                                         int M) {
    __shared__ unsigned As[64][36];
    __shared__ unsigned Bs[128][72];
    int tid = threadIdx.x;
    int warp = tid >> 5, lane = tid & 31;
    int q = lane >> 2, r4 = lane & 3;
    int rowBase = blockIdx.y * 64;
    int colBase = blockIdx.x * 64;
    int wm = (warp >> 2) * 32;
    int wn = (warp & 3) * 16;

    for (int j = tid; j < 2048; j += 256) {
        int k = j >> 4;
        int n4 = (j & 15) * 4;
        float4 v = *(const float4*)&B[(size_t)k * D1 + colBase + n4];
        uint4 t;
        t.x = f2tf32(v.x); t.y = f2tf32(v.y); t.z = f2tf32(v.z); t.w = f2tf32(v.w);
        *(uint4*)&Bs[k][n4] = t;
    }

    float c[2][2][4] = {};
    for (int kc = 0; kc < 4; kc++) {
        for (int j = tid; j < 512; j += 256) {
            int r = j >> 3;
            int k4 = (j & 7) * 4;
            int gr = rowBase + r;
            float4 v = make_float4(0.f, 0.f, 0.f, 0.f);
            if (gr < M) v = *(const float4*)&A[(size_t)gr * F_IN + kc * 32 + k4];
            uint4 t;
            t.x = f2tf32(v.x); t.y = f2tf32(v.y); t.z = f2tf32(v.z); t.w = f2tf32(v.w);
            *(uint4*)&As[r][k4] = t;
        }
        __syncthreads();
#pragma unroll
        for (int ks = 0; ks < 4; ks++) {
            int kk = ks * 8;
            unsigned a[2][4], b[2][2];
#pragma unroll
            for (int mt = 0; mt < 2; mt++) {
                int rr = wm + mt * 16 + q;
                a[mt][0] = As[rr][kk + r4];
                a[mt][1] = As[rr + 8][kk + r4];
                a[mt][2] = As[rr][kk + r4 + 4];
                a[mt][3] = As[rr + 8][kk + r4 + 4];
            }
#pragma unroll
            for (int nt = 0; nt < 2; nt++) {
                int cc = wn + nt * 8 + q;
                b[nt][0] = Bs[kc * 32 + kk + r4][cc];
                b[nt][1] = Bs[kc * 32 + kk + r4 + 4][cc];
            }
#pragma unroll
            for (int mt = 0; mt < 2; mt++)
#pragma unroll
                for (int nt = 0; nt < 2; nt++) {
                    asm volatile(
                        "mma.sync.aligned.m16n8k8.row.col.f32.tf32.tf32.f32 "
                        "{%0,%1,%2,%3}, {%4,%5,%6,%7}, {%8,%9}, {%0,%1,%2,%3};"
                        : "+f"(c[mt][nt][0]), "+f"(c[mt][nt][1]),
                          "+f"(c[mt][nt][2]), "+f"(c[mt][nt][3])
                        : "r"(a[mt][0]), "r"(a[mt][1]), "r"(a[mt][2]), "r"(a[mt][3]),
                          "r"(b[nt][0]), "r"(b[nt][1]));
                }
        }
        __syncthreads();
    }
#pragma unroll
    for (int mt = 0; mt < 2; mt++) {
        int r0 = rowBase + wm + mt * 16 + q;
#pragma unroll
        for (int nt = 0; nt < 2; nt++) {
            int col = colBase + wn + nt * 8 + r4 * 2;
            if (r0 < M) {
                float2 w0 = make_float2(c[mt][nt][0], c[mt][nt][1]);
                *(float2*)&g_h1[(size_t)r0 * D1 + col] = w0;
            }
            if (r0 + 8 < M) {
                float2 w1 = make_float2(c[mt][nt][2], c[mt][nt][3]);
                *(float2*)&g_h1[(size_t)(r0 + 8) * D1 + col] = w1;
            }
        }
    }
}

// ======== scores1 + bf16 copy: one pass over h1 =============================
__global__ __launch_bounds__(256) void scores1_kernel(const float* __restrict__ asrc,
                                                      const float* __restrict__ adst,
                                                      int n) {
    int wid  = (blockIdx.x * blockDim.x + threadIdx.x) >> 5;
    int lane = threadIdx.x & 31;
    if (wid >= n) return;
    size_t base = (size_t)wid * D1 + lane * 8;
    float4 v0 = *(const float4*)&g_h1[base];
    float4 v1 = *(const float4*)&g_h1[base + 4];
    float4 a0 = *(const float4*)&asrc[lane * 8];
    float4 a1 = *(const float4*)&asrc[lane * 8 + 4];
    float4 d0 = *(const float4*)&adst[lane * 8];
    float4 d1 = *(const float4*)&adst[lane * 8 + 4];
    float ps = v0.x*a0.x + v0.y*a0.y + v0.z*a0.z + v0.w*a0.w
             + v1.x*a1.x + v1.y*a1.y + v1.z*a1.z + v1.w*a1.w;
    float pd = v0.x*d0.x + v0.y*d0.y + v0.z*d0.z + v0.w*d0.w
             + v1.x*d1.x + v1.y*d1.y + v1.z*d1.z + v1.w*d1.w;
    ps += __shfl_xor_sync(0xffffffffu, ps, 1);
    ps += __shfl_xor_sync(0xffffffffu, ps, 2);
    pd += __shfl_xor_sync(0xffffffffu, pd, 1);
    pd += __shfl_xor_sync(0xffffffffu, pd, 2);
    int h = lane >> 2;
    if ((lane & 3) == 0) {
        g_ssrc1[wid * HEADS + h] = ps;
        g_sdst1[wid * HEADS + h] = pd;
        g_pself1[wid * HEADS + h] = __expf(lrelu(ps + pd));
    }
    __nv_bfloat162 p0 = __floats2bfloat162_rn(v0.x, v0.y);
    __nv_bfloat162 p1 = __floats2bfloat162_rn(v0.z, v0.w);
    __nv_bfloat162 p2 = __floats2bfloat162_rn(v1.x, v1.y);
    __nv_bfloat162 p3 = __floats2bfloat162_rn(v1.z, v1.w);
    uint4 pk;
    pk.x = *reinterpret_cast<unsigned*>(&p0);
    pk.y = *reinterpret_cast<unsigned*>(&p1);
    pk.z = *reinterpret_cast<unsigned*>(&p2);
    pk.w = *reinterpret_cast<unsigned*>(&p3);
    *(uint4*)&g_h1b[base] = pk;
}

// ======== aggregate1: 1 warp/node, 8 ch/lane, uint4 bf16 gather, unroll-4 ===
__global__ __launch_bounds__(256) void aggregate1_kernel(const float* __restrict__ b1, int M) {
    int node = (blockIdx.x * blockDim.x + threadIdx.x) >> 5;
    int lane = threadIdx.x & 31;
    if (node >= M) return;
    int ch = lane * 8;
    int h  = lane >> 2;
    float sdst_h = g_sdst1[node * HEADS + h];
    float pself  = g_pself1[node * HEADS + h];
    size_t nb = (size_t)node * D1 + ch;
    float4 a0 = *(const float4*)&g_h1[nb];
    float4 a1 = *(const float4*)&g_h1[nb + 4];
    float c0 = a0.x * pself, c1 = a0.y * pself, c2 = a0.z * pself, c3 = a0.w * pself;
    float c4 = a1.x * pself, c5 = a1.y * pself, c6 = a1.z * pself, c7 = a1.w * pself;
    float denom = pself;
    int beg = g_rowptr[node], end = g_rowptr[node + 1];
    int i = beg;
    for (; i + 4 <= end; i += 4) {
        int s0 = __ldg(&g_csr_src[i]);
        int s1 = __ldg(&g_csr_src[i + 1]);
        int s2 = __ldg(&g_csr_src[i + 2]);
        int s3 = __ldg(&g_csr_src[i + 3]);
        float e0 = __ldg(&g_ssrc1[s0 * HEADS + h]);
        float e1 = __ldg(&g_ssrc1[s1 * HEADS + h]);
        float e2 = __ldg(&g_ssrc1[s2 * HEADS + h]);
        float e3 = __ldg(&g_ssrc1[s3 * HEADS + h]);
        uint4 r0 = *(const uint4*)&g_h1b[(size_t)s0 * D1 + ch];
        uint4 r1 = *(const uint4*)&g_h1b[(size_t)s1 * D1 + ch];
        uint4 r2 = *(const uint4*)&g_h1b[(size_t)s2 * D1 + ch];
        uint4 r3 = *(const uint4*)&g_h1b[(size_t)s3 * D1 + ch];
        float p0 = __expf(lrelu(e0 + sdst_h));
        float p1 = __expf(lrelu(e1 + sdst_h));
        float p2 = __expf(lrelu(e2 + sdst_h));
        float p3 = __expf(lrelu(e3 + sdst_h));
        {
            float2 va = __bfloat1622float2(*reinterpret_cast<__nv_bfloat162*>(&r0.x));
            float2 vb = __bfloat1622float2(*reinterpret_cast<__nv_bfloat162*>(&r0.y));
            float2 vc = __bfloat1622float2(*reinterpret_cast<__nv_bfloat162*>(&r0.z));
            float2 vd = __bfloat1622float2(*reinterpret_cast<__nv_bfloat162*>(&r0.w));
            c0 += va.x * p0; c1 += va.y * p0; c2 += vb.x * p0; c3 += vb.y * p0;
            c4 += vc.x * p0; c5 += vc.y * p0; c6 += vd.x * p0; c7 += vd.y * p0;
        }
        {
            float2 va = __bfloat1622float2(*reinterpret_cast<__nv_bfloat162*>(&r1.x));
            float2 vb = __bfloat1622float2(*reinterpret_cast<__nv_bfloat162*>(&r1.y));
            float2 vc = __bfloat1622float2(*reinterpret_cast<__nv_bfloat162*>(&r1.z));
            float2 vd = __bfloat1622float2(*reinterpret_cast<__nv_bfloat162*>(&r1.w));
            c0 += va.x * p1; c1 += va.y * p1; c2 += vb.x * p1; c3 += vb.y * p1;
            c4 += vc.x * p1; c5 += vc.y * p1; c6 += vd.x * p1; c7 += vd.y * p1;
        }
        {
            float2 va = __bfloat1622float2(*reinterpret_cast<__nv_bfloat162*>(&r2.x));
            float2 vb = __bfloat1622float2(*reinterpret_cast<__nv_bfloat162*>(&r2.y));
            float2 vc = __bfloat1622float2(*reinterpret_cast<__nv_bfloat162*>(&r2.z));
            float2 vd = __bfloat1622float2(*reinterpret_cast<__nv_bfloat162*>(&r2.w));
            c0 += va.x * p2; c1 += va.y * p2; c2 += vb.x * p2; c3 += vb.y * p2;
            c4 += vc.x * p2; c5 += vc.y * p2; c6 += vd.x * p2; c7 += vd.y * p2;
        }
        {
            float2 va = __bfloat1622float2(*reinterpret_cast<__nv_bfloat162*>(&r3.x));
            float2 vb = __bfloat1622float2(*reinterpret_cast<__nv_bfloat162*>(&r3.y));
            float2 vc = __bfloat1622float2(*reinterpret_cast<__nv_bfloat162*>(&r3.z));
            float2 vd = __bfloat1622float2(*reinterpret_cast<__nv_bfloat162*>(&r3.w));
            c0 += va.x * p3; c1 += va.y * p3; c2 += vb.x * p3; c3 += vb.y * p3;
            c4 += vc.x * p3; c5 += vc.y * p3; c6 += vd.x * p3; c7 += vd.y * p3;
        }
        denom += (p0 + p1) + (p2 + p3);
    }
    for (; i < end; i++) {
        int s = __ldg(&g_csr_src[i]);
        float e = __ldg(&g_ssrc1[s * HEADS + h]);
        uint4 r = *(const uint4*)&g_h1b[(size_t)s * D1 + ch];
        float p = __expf(lrelu(e + sdst_h));
        float2 va = __bfloat1622float2(*reinterpret_cast<__nv_bfloat162*>(&r.x));
        float2 vb = __bfloat1622float2(*reinterpret_cast<__nv_bfloat162*>(&r.y));
        float2 vc = __bfloat1622float2(*reinterpret_cast<__nv_bfloat162*>(&r.z));
        float2 vd = __bfloat1622float2(*reinterpret_cast<__nv_bfloat162*>(&r.w));
        c0 += va.x * p; c1 += va.y * p; c2 += vb.x * p; c3 += vb.y * p;
        c4 += vc.x * p; c5 += vc.y * p; c6 += vd.x * p; c7 += vd.y * p;
        denom += p;
    }
    float inv = __frcp_rn(denom);
    float4 bb0 = *(const float4*)&b1[ch];
    float4 bb1 = *(const float4*)&b1[ch + 4];
    float4 o0, o1;
    o0.x = fmaxf(c0 * inv + bb0.x, 0.f); o0.y = fmaxf(c1 * inv + bb0.y, 0.f);
    o0.z = fmaxf(c2 * inv + bb0.z, 0.f); o0.w = fmaxf(c3 * inv + bb0.w, 0.f);
    o1.x = fmaxf(c4 * inv + bb1.x, 0.f); o1.y = fmaxf(c5 * inv + bb1.y, 0.f);
    o1.z = fmaxf(c6 * inv + bb1.z, 0.f); o1.w = fmaxf(c7 * inv + bb1.w, 0.f);
    *(float4*)&g_h2[nb]     = o0;
    *(float4*)&g_h2[nb + 4] = o1;
}

// ======== GEMM2 via tf32 mma.sync (+ bf16 copy): h3 = h2 @ W2 ==============
__global__ __launch_bounds__(256) void gemm2_tf32_kernel(const float* __restrict__ B, int M) {
    __shared__ unsigned As[128][36];
    __shared__ unsigned Bs[32][44];
    int tid = threadIdx.x;
    int warp = tid >> 5, lane = tid & 31;
    int q = lane >> 2, r4 = lane & 3;
    int rowBase = blockIdx.x * 128;
    int wm = warp * 16;

    float c[5][4] = {};
    for (int kc = 0; kc < 8; kc++) {
        for (int j = tid; j < 1024; j += 256) {
            int r = j >> 3;
            int k4 = (j & 7) * 4;
            int gr = rowBase + r;
            float4 v = make_float4(0.f, 0.f, 0.f, 0.f);
            if (gr < M) v = *(const float4*)&g_h2[(size_t)gr * D1 + kc * 32 + k4];
            uint4 t;
            t.x = f2tf32(v.x); t.y = f2tf32(v.y); t.z = f2tf32(v.z); t.w = f2tf32(v.w);
            *(uint4*)&As[r][k4] = t;
        }
        for (int j = tid; j < 1280; j += 256) {
            int k = j / NCLS;
            int n = j - k * NCLS;
            Bs[k][n] = f2tf32(B[(size_t)(kc * 32 + k) * NCLS + n]);
        }
        __syncthreads();
#pragma unroll
        for (int ks = 0; ks < 4; ks++) {
            int kk = ks * 8;
            unsigned a[4];
            int rr = wm + q;
            a[0] = As[rr][kk + r4];
            a[1] = As[rr + 8][kk + r4];
            a[2] = As[rr][kk + r4 + 4];
            a[3] = As[rr + 8][kk + r4 + 4];
#pragma unroll
            for (int nt = 0; nt < 5; nt++) {
                unsigned b0 = Bs[kk + r4][nt * 8 + q];
                unsigned b1 = Bs[kk + r4 + 4][nt * 8 + q];
                asm volatile(
                    "mma.sync.aligned.m16n8k8.row.col.f32.tf32.tf32.f32 "
                    "{%0,%1,%2,%3}, {%4,%5,%6,%7}, {%8,%9}, {%0,%1,%2,%3};"
                    : "+f"(c[nt][0]), "+f"(c[nt][1]), "+f"(c[nt][2]), "+f"(c[nt][3])
                    : "r"(a[0]), "r"(a[1]), "r"(a[2]), "r"(a[3]),
                      "r"(b0), "r"(b1));
            }
        }
        __syncthreads();
    }
    int r0 = rowBase + wm + q;
#pragma unroll
    for (int nt = 0; nt < 5; nt++) {
        int col = nt * 8 + r4 * 2;
        if (r0 < M) {
            float2 w0 = make_float2(c[nt][0], c[nt][1]);
            *(float2*)&g_h3[(size_t)r0 * NCLS + col] = w0;
            __nv_bfloat162 pb = __floats2bfloat162_rn(c[nt][0], c[nt][1]);
            *(unsigned*)&g_h3b[(size_t)r0 * NCLS + col] = *reinterpret_cast<unsigned*>(&pb);
        }
        if (r0 + 8 < M) {
            float2 w1 = make_float2(c[nt][2], c[nt][3]);
            *(float2*)&g_h3[(size_t)(r0 + 8) * NCLS + col] = w1;
            __nv_bfloat162 pb = __floats2bfloat162_rn(c[nt][2], c[nt][3]);
            *(unsigned*)&g_h3b[(size_t)(r0 + 8) * NCLS + col] = *reinterpret_cast<unsigned*>(&pb);
        }
    }
}

// ======== scores2: warp per node over h3 ====================================
__global__ __launch_bounds__(256) void scores2_kernel(const float* __restrict__ asrc,
                                                      const float* __restrict__ adst,
                                                      int n) {
    int wid  = (blockIdx.x * blockDim.x + threadIdx.x) >> 5;
    int lane = threadIdx.x & 31;
    if (wid >= n) return;
    size_t base = (size_t)wid * NCLS;
    float v0 = g_h3[base + lane];
    float v1 = (lane < 8) ? g_h3[base + 32 + lane] : 0.f;
    float a0 = asrc[lane], d0 = adst[lane];
    float a1 = (lane < 8) ? asrc[32 + lane] : 0.f;
    float d1 = (lane < 8) ? adst[32 + lane] : 0.f;
    float ps = v0 * a0 + v1 * a1;
    float pd = v0 * d0 + v1 * d1;
#pragma unroll
    for (int o = 16; o; o >>= 1) {
        ps += __shfl_xor_sync(0xffffffffu, ps, o);
        pd += __shfl_xor_sync(0xffffffffu, pd, o);
    }
    if (lane == 0) {
        g_ssrc2[wid] = ps;
        g_sdst2[wid] = pd;
        g_pself2[wid] = __expf(lrelu(ps + pd));
    }
}

// ======== aggregate2: warp/node, 2 ch/lane (lanes 0-19), bf16 gather ========
__global__ __launch_bounds__(256) void aggregate2_kernel(const float* __restrict__ b2,
                                                         float* __restrict__ out, int M) {
    int wid  = (blockIdx.x * blockDim.x + threadIdx.x) >> 5;
    int lane = threadIdx.x & 31;
    if (wid >= M) return;
    float sdst = g_sdst2[wid];
    float pself = g_pself2[wid];
    size_t nb = (size_t)wid * NCLS;
    bool act = lane < 20;
    int ch = lane * 2;
    float v0 = 0.f, v1 = 0.f;
    if (act) {
        float2 s = *(const float2*)&g_h3[nb + ch];
        v0 = s.x * pself; v1 = s.y * pself;
    }
    float denom = pself;
    int beg = g_rowptr[wid], end = g_rowptr[wid + 1];
    int i = beg;
    for (; i + 4 <= end; i += 4) {
        int s0 = __ldg(&g_csr_src[i]);
        int s1 = __ldg(&g_csr_src[i + 1]);
        int s2 = __ldg(&g_csr_src[i + 2]);
        int s3 = __ldg(&g_csr_src[i + 3]);
        float e0 = __ldg(&g_ssrc2[s0]);
        float e1 = __ldg(&g_ssrc2[s1]);
        float e2 = __ldg(&g_ssrc2[s2]);
        float e3 = __ldg(&g_ssrc2[s3]);
        unsigned r0 = 0, r1 = 0, r2 = 0, r3 = 0;
        if (act) {
            r0 = *(const unsigned*)&g_h3b[(size_t)s0 * NCLS + ch];
            r1 = *(const unsigned*)&g_h3b[(size_t)s1 * NCLS + ch];
            r2 = *(const unsigned*)&g_h3b[(size_t)s2 * NCLS + ch];
            r3 = *(const unsigned*)&g_h3b[(size_t)s3 * NCLS + ch];
        }
        float p0 = __expf(lrelu(e0 + sdst));
        float p1 = __expf(lrelu(e1 + sdst));
        float p2 = __expf(lrelu(e2 + sdst));
        float p3 = __expf(lrelu(e3 + sdst));
        float2 w0 = __bfloat1622float2(*reinterpret_cast<__nv_bfloat162*>(&r0));
        float2 w1 = __bfloat1622float2(*reinterpret_cast<__nv_bfloat162*>(&r1));
        float2 w2 = __bfloat1622float2(*reinterpret_cast<__nv_bfloat162*>(&r2));
        float2 w3 = __bfloat1622float2(*reinterpret_cast<__nv_bfloat162*>(&r3));
        v0 += w0.x * p0 + w1.x * p1 + w2.x * p2 + w3.x * p3;
        v1 += w0.y * p0 + w1.y * p1 + w2.y * p2 + w3.y * p3;
        denom += (p0 + p1) + (p2 + p3);
    }
    for (; i < end; i++) {
        int s = __ldg(&g_csr_src[i]);
        float e = __ldg(&g_ssrc2[s]);
        unsigned r = 0;
        if (act) r = *(const unsigned*)&g_h3b[(size_t)s * NCLS + ch];
        float p = __expf(lrelu(e + sdst));
        float2 w = __bfloat1622float2(*reinterpret_cast<__nv_bfloat162*>(&r));
        v0 += w.x * p; v1 += w.y * p;
        denom += p;
    }
    float inv = __frcp_rn(denom);
    float z0 = -FLT_MAX, z1 = -FLT_MAX;
    if (act) {
        z0 = v0 * inv + b2[ch];
        z1 = v1 * inv + b2[ch + 1];
    }
    float m = fmaxf(z0, z1);
#pragma unroll
    for (int o = 16; o; o >>= 1) m = fmaxf(m, __shfl_xor_sync(0xffffffffu, m, o));
    float s = act ? (expf(z0 - m) + expf(z1 - m)) : 0.f;
#pragma unroll
    for (int o = 16; o; o >>= 1) s += __shfl_xor_sync(0xffffffffu, s, o);
    float ls = logf(s);
    if (act) {
        out[nb + ch]     = z0 - m - ls;
        out[nb + ch + 1] = z1 - m - ls;
    }
}

// ---------------------------------------------------------------------------
extern "C" void kernel_launch(void* const* d_in, const int* in_sizes, int n_in,
                              void* d_out, int out_size) {
    const float* x     = (const float*)d_in[0];
    const int*   ei    = (const int*)d_in[1];      // JAX x64 disabled -> int32
    const float* W1    = (const float*)d_in[2];
    const float* asrc1 = (const float*)d_in[3];
    const float* adst1 = (const float*)d_in[4];
    const float* b1    = (const float*)d_in[5];
    const float* W2    = (const float*)d_in[6];
    const float* asrc2 = (const float*)d_in[7];
    const float* adst2 = (const float*)d_in[8];
    const float* b2    = (const float*)d_in[9];
    float* out = (float*)d_out;

    int M = in_sizes[0] / F_IN;        // 100000
    int E = in_sizes[1] / 2;           // 1600000
    const int* src = ei;
    const int* dst = ei + E;
    int NB = (M + SCAN_B - 1) / SCAN_B;

    static cudaStream_t s2 = nullptr;
    static cudaEvent_t evFork = nullptr, evJoin = nullptr;
    if (s2 == nullptr) {
        cudaStreamCreateWithFlags(&s2, cudaStreamNonBlocking);
        cudaEventCreateWithFlags(&evFork, cudaEventDisableTiming);
        cudaEventCreateWithFlags(&evJoin, cudaEventDisableTiming);
    }

    // Fork: CSR build on s2, GEMM1+scores on main stream.
    cudaEventRecord(evFork, 0);
    cudaStreamWaitEvent(s2, evFork, 0);

    zero_counts_kernel<<<(M + 255) / 256, 256, 0, s2>>>(M);
    hist_kernel<<<(E + 255) / 256, 256, 0, s2>>>(dst, E);
    scan_sums_kernel<<<NB, SCAN_B, 0, s2>>>(M);
    scan_offsets_kernel<<<1, SCAN_B, 0, s2>>>(NB, M);
    scan_apply_kernel<<<NB, SCAN_B, 0, s2>>>(M);
    scatter_kernel<<<(E + 255) / 256, 256, 0, s2>>>(src, dst, E);
    cudaEventRecord(evJoin, s2);

    {
        dim3 grid(D1 / 64, (M + 63) / 64);
        gemm1_tf32_kernel<<<grid, 256>>>(x, W1, M);
    }
    scores1_kernel<<<(M * 32 + 255) / 256, 256>>>(asrc1, adst1, M);

    cudaStreamWaitEvent(0, evJoin, 0);

    aggregate1_kernel<<<(M * 32 + 255) / 256, 256>>>(b1, M);

    // Layer 2
    gemm2_tf32_kernel<<<(M + 127) / 128, 256>>>(W2, M);
    scores2_kernel<<<(M * 32 + 255) / 256, 256>>>(asrc2, adst2, M);
    aggregate2_kernel<<<(M * 32 + 255) / 256, 256>>>(b2, out, M);
}